// round 1
// baseline (speedup 1.0000x reference)
#include <cuda_runtime.h>
#include <math.h>

#define B_    128
#define L_    512
#define D_    128
#define H_    8
#define E_    16
#define DFF_  512
#define LP_   514   // L + 2 (circular pad for conv)

// ---------------- scratch (static device allocations only) ----------------
__device__ float g_Xtp  [B_*LP_*D_];    // circular-padded, transposed input (B, L+2, D)
__device__ float g_MarkT[B_*L_*D_];     // mark transposed to (B, L, D)
__device__ float g_H    [B_*L_*D_];     // hidden state (B, L, D)
__device__ float g_T1   [B_*L_*D_];     // temp
__device__ float g_T2   [B_*L_*D_];     // temp
__device__ float g_U    [B_*L_*DFF_];   // FFN hidden (B, L, 512)
__device__ float g_F    [B_*D_*128];    // DFT coeffs: rows (b*128+d), cols [re m | im m]
__device__ float g_SEL  [B_*D_*128];    // mixed coeffs, same layout
__device__ float g_Wc   [384*128];      // conv weight rearranged (3*128, 128)
__device__ float g_Basis[512*128];      // forward DFT basis [t][n]
__device__ float g_IB   [128*512];      // inverse basis [n][t]
__device__ float g_PE   [512*128];      // positional encoding
__device__ float g_CM   [B_*D_];        // per-(b,d) column sums

__device__ __forceinline__ float geluf(float v) {
    return 0.5f * v * (1.0f + erff(v * 0.7071067811865476f));
}

// ---------------- table init (cheap, rebuilt every call: deterministic) ----
__global__ void k_tables(const float* __restrict__ conv_w) {
    int idx = blockIdx.x * 256 + threadIdx.x;   // grid covers 65536
    if (idx < 512*128) {
        // Basis[t][n]: n<64 -> cos(2*pi*m*t/512), n>=64 -> -sin(...)
        int t = idx >> 7, n = idx & 127, m = n & 63;
        float x = (float)(m * t) * (1.0f/256.0f);
        g_Basis[idx] = (n < 64) ? cospif(x) : -sinpif(x);
    }
    if (idx < 128*512) {
        // IB[n][t]
        int n = idx >> 9, t = idx & 511, m = n & 63;
        float x = (float)(m * t) * (1.0f/256.0f);
        float v;
        if (n == 0)       v = 1.0f/512.0f;
        else if (n < 64)  v = 2.0f * cospif(x) * (1.0f/512.0f);
        else if (n == 64) v = 0.0f;                       // bin-0 imag ignored by C2R
        else              v = -2.0f * sinpif(x) * (1.0f/512.0f);
        g_IB[idx] = v;
    }
    if (idx < 512*128) {
        // PE[t][d]
        int t = idx >> 7, d = idx & 127;
        int i2 = d & ~1;
        float div = expf((float)i2 * (-9.210340371976184f / 128.0f)); // ln(10000)
        float a = (float)t * div;
        g_PE[idx] = (d & 1) ? cosf(a) : sinf(a);
    }
    if (idx < 384*128) {
        // Wc[j][dout], j = s*128 + din ; conv_w layout (dout, din, s)
        int j = idx >> 7, dout = idx & 127;
        int s = j >> 7, din = j & 127;
        g_Wc[idx] = conv_w[dout*384 + din*3 + s];
    }
}

// ---------------- transpose (B,D,L) -> (B,L,D), Xtp shifted by +1 row ------
__global__ void k_transpose(const float* __restrict__ x_enc,
                            const float* __restrict__ mark) {
    __shared__ float tile [32][33];
    __shared__ float tileM[32][33];
    int b  = blockIdx.z;
    int d0 = blockIdx.y * 32, l0 = blockIdx.x * 32;
    int tx = threadIdx.x, ty = threadIdx.y;           // 32 x 8
    const float* xb = x_enc + b*65536;
    const float* mb = mark  + b*65536;
    #pragma unroll
    for (int i = ty; i < 32; i += 8) {
        tile [i][tx] = xb[(d0+i)*512 + l0 + tx];
        tileM[i][tx] = mb[(d0+i)*512 + l0 + tx];
    }
    __syncthreads();
    float* xo = g_Xtp   + b*LP_*128;
    float* mo = g_MarkT + b*65536;
    #pragma unroll
    for (int i = ty; i < 32; i += 8) {
        xo[(l0+i+1)*128 + d0+tx] = tile [tx][i];
        mo[(l0+i  )*128 + d0+tx] = tileM[tx][i];
    }
}

__global__ void k_edges(const float* __restrict__ x_enc) {
    int idx = blockIdx.x*256 + threadIdx.x;           // 16384
    if (idx < B_*D_) {
        int b = idx >> 7, d = idx & 127;
        g_Xtp[b*LP_*128 +   0*128 + d] = x_enc[b*65536 + d*512 + 511]; // circular
        g_Xtp[b*LP_*128 + 513*128 + d] = x_enc[b*65536 + d*512 +   0];
    }
}

// ---------------- generic tiled SGEMM --------------------------------------
// C[row, col] = epi( sum_k A(row,k) * Bw[k, col] )
// A(row,k) = A[(row>>absh)*abstr + (row & mask)*arstr + k*akstr]
// LOADA=0: k-contiguous global loads; LOADA=1: row-contiguous global loads.
// EPI bits: 1=+bias[col], 2=+res[row*ldc+col], 4=gelu, 8=+PE[(row&511)*128+col]
template<int BM, int BN, int BK, int LOADA, int EPI>
__global__ void __launch_bounds__(256) k_gemm(
    const float* __restrict__ A, const float* __restrict__ Bw,
    const float* __restrict__ bias, const float* __restrict__ res,
    float* __restrict__ C,
    int K, int ldb, int ldc,
    int absh, int abstr, int arstr, int akstr)
{
    constexpr int TM  = BM / 16;
    constexpr int TN  = BN / 16;
    constexpr int LDA = BM + 4;
    constexpr int LDB = BN + 4;
    __shared__ float As[BK * LDA];
    __shared__ float Bs[BK * LDB];
    int tid = threadIdx.x;
    int tx = tid & 15, ty = tid >> 4;
    int rowBase = blockIdx.x * BM;
    int colBase = blockIdx.y * BN;
    int amask = (1 << absh) - 1;

    float acc[TM][TN];
    #pragma unroll
    for (int i = 0; i < TM; i++)
        #pragma unroll
        for (int j = 0; j < TN; j++) acc[i][j] = 0.f;

    for (int k0 = 0; k0 < K; k0 += BK) {
        #pragma unroll
        for (int e = tid; e < BM*BK; e += 256) {
            int m, k;
            if (LOADA == 0) { m = e >> 4;  k = e & (BK-1); }   // BK == 16
            else            { k = e / BM;  m = e - k*BM;   }
            int row  = rowBase + m;
            int base = (row >> absh) * abstr + (row & amask) * arstr;
            As[k*LDA + m] = A[base + (k0 + k) * akstr];
        }
        #pragma unroll
        for (int e = tid; e < BK*BN; e += 256) {
            int k = e / BN, n = e - k*BN;
            Bs[k*LDB + n] = Bw[(k0 + k) * ldb + colBase + n];
        }
        __syncthreads();
        #pragma unroll
        for (int k = 0; k < BK; k++) {
            float aF[TM], bF[TN];
            #pragma unroll
            for (int f = 0; f < TM/4; f++) {
                float4 v = *(const float4*)&As[k*LDA + f*(BM/2) + ty*4];
                aF[f*4+0]=v.x; aF[f*4+1]=v.y; aF[f*4+2]=v.z; aF[f*4+3]=v.w;
            }
            #pragma unroll
            for (int f = 0; f < TN/4; f++) {
                float4 v = *(const float4*)&Bs[k*LDB + f*(BN/2) + tx*4];
                bF[f*4+0]=v.x; bF[f*4+1]=v.y; bF[f*4+2]=v.z; bF[f*4+3]=v.w;
            }
            #pragma unroll
            for (int i = 0; i < TM; i++)
                #pragma unroll
                for (int j = 0; j < TN; j++)
                    acc[i][j] += aF[i] * bF[j];
        }
        __syncthreads();
    }

    #pragma unroll
    for (int fi = 0; fi < TM/4; fi++)
    #pragma unroll
    for (int ii = 0; ii < 4; ii++) {
        int row = rowBase + fi*(BM/2) + ty*4 + ii;
        #pragma unroll
        for (int fj = 0; fj < TN/4; fj++) {
            int col = colBase + fj*(BN/2) + tx*4;
            float vv[4];
            #pragma unroll
            for (int jj = 0; jj < 4; jj++) vv[jj] = acc[fi*4+ii][fj*4+jj];
            if (EPI & 1) {
                #pragma unroll
                for (int jj = 0; jj < 4; jj++) vv[jj] += bias[col + jj];
            }
            if (EPI & 8) {
                int peb = (row & 511) * 128 + col;
                #pragma unroll
                for (int jj = 0; jj < 4; jj++) vv[jj] += g_PE[peb + jj];
            }
            int idx = row * ldc + col;
            if (EPI & 2) {
                float4 r = *(const float4*)&res[idx];
                vv[0]+=r.x; vv[1]+=r.y; vv[2]+=r.z; vv[3]+=r.w;
            }
            if (EPI & 4) {
                #pragma unroll
                for (int jj = 0; jj < 4; jj++) vv[jj] = geluf(vv[jj]);
            }
            float4 o; o.x=vv[0]; o.y=vv[1]; o.z=vv[2]; o.w=vv[3];
            *(float4*)&C[idx] = o;
        }
    }
}

// ---------------- complex mode mixing: sel = xft * Wc (per h, m) -----------
__global__ void k_mix(const float* __restrict__ fwr,
                      const float* __restrict__ fwi, int layer) {
    int b = blockIdx.x, h = blockIdx.y;
    int m = threadIdx.x;                               // 64 threads = modes
    const float* wr = fwr + (size_t)((layer*H_ + h)*E_*E_) * 64;
    const float* wi = fwi + (size_t)((layer*H_ + h)*E_*E_) * 64;
    float sr[E_], si[E_];
    #pragma unroll
    for (int o = 0; o < E_; o++) { sr[o] = 0.f; si[o] = 0.f; }
    const float* Fb = g_F + (b*128 + h*16) * 128;
    #pragma unroll
    for (int e = 0; e < E_; e++) {
        float fre = Fb[e*128 + m];
        float fim = Fb[e*128 + 64 + m];
        #pragma unroll
        for (int o = 0; o < E_; o++) {
            float cr = wr[(e*E_ + o)*64 + m];
            float ci = wi[(e*E_ + o)*64 + m];
            sr[o] += fre*cr - fim*ci;
            si[o] += fre*ci + fim*cr;
        }
    }
    float* Sb = g_SEL + (b*128 + h*16) * 128;
    #pragma unroll
    for (int o = 0; o < E_; o++) {
        Sb[o*128 + m]      = sr[o];
        Sb[o*128 + 64 + m] = si[o];
    }
}

// ---------------- series_decomp: Out = X - moving_mean(X, 25) --------------
__global__ void k_movsub(const float* __restrict__ X, float* __restrict__ Out) {
    __shared__ float sh[88 * 128];                    // 45 KB
    int b = blockIdx.x, t0 = blockIdx.y * 64;
    int d = threadIdx.x;                              // 128 threads = features
    const float* Xb = X + b*65536;
    #pragma unroll 4
    for (int r = 0; r < 88; r++) {
        int t = t0 + r - 12;
        t = max(0, min(511, t));                      // replicate padding
        sh[r*128 + d] = Xb[t*128 + d];
    }
    // serial prefix sum, column-private (no sync needed)
    float s = 0.f;
    #pragma unroll 4
    for (int r = 0; r < 88; r++) { s += sh[r*128 + d]; sh[r*128 + d] = s; }
    float* Ob = Out + b*65536;
    #pragma unroll 4
    for (int tt = 0; tt < 64; tt++) {
        int r = tt + 12;
        float hi = sh[(r+12)*128 + d];
        float lo = (r >= 13) ? sh[(r-13)*128 + d] : 0.f;
        Ob[(t0+tt)*128 + d] = Xb[(t0+tt)*128 + d] - (hi - lo) * (1.0f/25.0f);
    }
}

// ---------------- LayerNorm over D ------------------------------------------
__global__ void k_ln(const float* __restrict__ X, const float* __restrict__ g,
                     const float* __restrict__ be, float* __restrict__ Out) {
    int row  = blockIdx.x*8 + (threadIdx.x >> 5);
    int lane = threadIdx.x & 31;
    const float* xr = X + (size_t)row * 128;
    float v[4];
    float s = 0.f;
    #pragma unroll
    for (int i = 0; i < 4; i++) { v[i] = xr[lane + i*32]; s += v[i]; }
    #pragma unroll
    for (int o = 16; o > 0; o >>= 1) s += __shfl_xor_sync(0xffffffffu, s, o);
    float mu = s * (1.0f/128.0f);
    float q = 0.f;
    #pragma unroll
    for (int i = 0; i < 4; i++) { float dl = v[i] - mu; q += dl*dl; }
    #pragma unroll
    for (int o = 16; o > 0; o >>= 1) q += __shfl_xor_sync(0xffffffffu, q, o);
    float rstd = rsqrtf(q * (1.0f/128.0f) + 1e-5f);
    float* orow = Out + (size_t)row * 128;
    #pragma unroll
    for (int i = 0; i < 4; i++) {
        int d = lane + i*32;
        orow[d] = (v[i] - mu) * rstd * g[d] + be[d];
    }
}

__global__ void k_zero(float* p, int n) {
    int i = blockIdx.x*256 + threadIdx.x;
    if (i < n) p[i] = 0.f;
}

__global__ void k_colmean(const float* __restrict__ HN) {
    int b = blockIdx.x, t0 = blockIdx.y * 64, d = threadIdx.x;
    const float* Xb = HN + b*65536;
    float s = 0.f;
    #pragma unroll 8
    for (int tt = 0; tt < 64; tt++) s += Xb[(t0+tt)*128 + d];
    atomicAdd(&g_CM[b*128 + d], s);
}

// ---------------- final: gelu(hn - colmean) * mark, dot with proj_w --------
__global__ void k_final(const float* __restrict__ HN, const float* __restrict__ pw,
                        const float* __restrict__ pb, float* __restrict__ out) {
    int b = blockIdx.x, tid = threadIdx.x;
    const float* hb = HN + b*65536;
    const float* mb = g_MarkT + b*65536;
    float s = 0.f;
    for (int i = tid; i < 65536; i += 256) {
        float v = hb[i] - g_CM[b*128 + (i & 127)] * (1.0f/512.0f);
        s += geluf(v) * mb[i] * pw[i];
    }
    __shared__ float red[256];
    red[tid] = s; __syncthreads();
    #pragma unroll
    for (int o = 128; o > 0; o >>= 1) {
        if (tid < o) red[tid] += red[tid + o];
        __syncthreads();
    }
    if (tid == 0) out[b] = red[0] + pb[0];
}

// ---------------- host orchestration ----------------------------------------
extern "C" void kernel_launch(void* const* d_in, const int* in_sizes, int n_in,
                              void* d_out, int out_size) {
    const float* x_enc  = (const float*)d_in[0];
    const float* mark   = (const float*)d_in[1];
    const float* conv_w = (const float*)d_in[4];
    const float* Wq     = (const float*)d_in[5];
    const float* bq     = (const float*)d_in[6];
    const float* Wo     = (const float*)d_in[7];
    const float* bo     = (const float*)d_in[8];
    const float* fwr    = (const float*)d_in[9];
    const float* fwi    = (const float*)d_in[10];
    const float* W1     = (const float*)d_in[11];
    const float* W2     = (const float*)d_in[12];
    const float* ln_g   = (const float*)d_in[13];
    const float* ln_b   = (const float*)d_in[14];
    const float* pw     = (const float*)d_in[15];
    const float* pb     = (const float*)d_in[16];
    float* out = (float*)d_out;

    float *pXtp, *pH, *pT1, *pT2, *pU, *pF, *pSEL, *pWc, *pBasis, *pIB, *pCM;
    cudaGetSymbolAddress((void**)&pXtp,   g_Xtp);
    cudaGetSymbolAddress((void**)&pH,     g_H);
    cudaGetSymbolAddress((void**)&pT1,    g_T1);
    cudaGetSymbolAddress((void**)&pT2,    g_T2);
    cudaGetSymbolAddress((void**)&pU,     g_U);
    cudaGetSymbolAddress((void**)&pF,     g_F);
    cudaGetSymbolAddress((void**)&pSEL,   g_SEL);
    cudaGetSymbolAddress((void**)&pWc,    g_Wc);
    cudaGetSymbolAddress((void**)&pBasis, g_Basis);
    cudaGetSymbolAddress((void**)&pIB,    g_IB);
    cudaGetSymbolAddress((void**)&pCM,    g_CM);

    k_tables<<<256, 256>>>(conv_w);
    k_transpose<<<dim3(16,4,128), dim3(32,8)>>>(x_enc, mark);
    k_edges<<<64, 256>>>(x_enc);

    // TokenEmbedding conv (K=384 over padded rows) + positional encoding
    k_gemm<128,128,16,0,8><<<dim3(512,1), 256>>>(
        pXtp, pWc, nullptr, nullptr, pH, 384, 128, 128, 9, LP_*128, 128, 1);

    for (int l = 0; l < 2; l++) {
        // Q = h @ Wq + bq
        k_gemm<128,128,16,0,1><<<dim3(512,1), 256>>>(
            pH, Wq + l*16384, bq + l*128, nullptr, pT1, 128, 128, 128, 30, 0, 128, 1);
        // forward DFT (gather (B,L,D) as (b,d) x t rows)
        k_gemm<64,128,16,1,0><<<dim3(256,1), 256>>>(
            pT1, pBasis, nullptr, nullptr, pF, 512, 128, 128, 7, 65536, 1, 128);
        // complex mode mixing
        k_mix<<<dim3(128,8), 64>>>(fwr, fwi, l);
        // inverse DFT; output flat layout == scrambled .view(B,L,-1)
        k_gemm<128,128,16,0,0><<<dim3(128,4), 256>>>(
            pSEL, pIB, nullptr, nullptr, pT1, 128, 512, 512, 30, 0, 128, 1);
        // out proj + bias + residual
        k_gemm<128,128,16,0,3><<<dim3(512,1), 256>>>(
            pT1, Wo + l*16384, bo + l*128, pH, pT2, 128, 128, 128, 30, 0, 128, 1);
        // decomp1
        k_movsub<<<dim3(128,8), 128>>>(pT2, pH);
        // FFN up + gelu
        k_gemm<128,128,16,0,4><<<dim3(512,4), 256>>>(
            pH, W1 + l*65536, nullptr, nullptr, pU, 128, 512, 512, 30, 0, 128, 1);
        // FFN down + residual
        k_gemm<128,128,16,0,2><<<dim3(512,1), 256>>>(
            pU, W2 + l*65536, nullptr, pH, pT2, 512, 128, 128, 30, 0, 512, 1);
        // decomp2
        k_movsub<<<dim3(128,8), 128>>>(pT2, pH);
    }

    k_ln<<<8192, 256>>>(pH, ln_g, ln_b, pT1);
    k_zero<<<64, 256>>>(pCM, B_*D_);
    k_colmean<<<dim3(128,8), 128>>>(pT1);
    k_final<<<128, 256>>>(pT1, pw, pb, out);
}

// round 3
// speedup vs baseline: 1.6834x; 1.6834x over previous
#include <cuda_runtime.h>
#include <cuda_bf16.h>
#include <math.h>
#include <stdint.h>

#define B_    128
#define L_    512
#define D_    128
#define H_    8
#define E_    16
#define DFF_  512
#define LP_   514

// ---------------- fp32 scratch ----------------
__device__ float g_Xtp  [B_*LP_*D_];
__device__ float g_MarkT[B_*L_*D_];
__device__ float g_H    [B_*L_*D_];
__device__ float g_T1   [B_*L_*D_];
__device__ float g_T2   [B_*L_*D_];
__device__ float g_U    [B_*L_*DFF_];
__device__ float g_F    [B_*D_*128];
__device__ float g_SEL  [B_*D_*128];
__device__ float g_PE   [512*128];
__device__ float g_CM   [B_*D_];

// ---------------- bf16 weights (hi/lo split), [N, K] row-major -------------
__device__ __nv_bfloat16 g_cw_h[128*384], g_cw_l[128*384];
__device__ __nv_bfloat16 g_fb_h[128*512], g_fb_l[128*512];
__device__ __nv_bfloat16 g_ib_h[512*128], g_ib_l[512*128];
__device__ __nv_bfloat16 g_wq_h[2*128*128], g_wq_l[2*128*128];
__device__ __nv_bfloat16 g_wo_h[2*128*128], g_wo_l[2*128*128];
__device__ __nv_bfloat16 g_w1_h[2*512*128], g_w1_l[2*512*128];
__device__ __nv_bfloat16 g_w2_h[2*128*512], g_w2_l[2*128*512];

__device__ __forceinline__ float geluf(float v) {
    return 0.5f * v * (1.0f + erff(v * 0.7071067811865476f));
}
__device__ __forceinline__ void fsplit(float x, __nv_bfloat16& h, __nv_bfloat16& l) {
    h = __float2bfloat16_rn(x);
    l = __float2bfloat16_rn(x - __bfloat162float(h));
}
__device__ __forceinline__ uint32_t pack2(__nv_bfloat16 a, __nv_bfloat16 b) {
    return (uint32_t)__bfloat16_as_ushort(a) | ((uint32_t)__bfloat16_as_ushort(b) << 16);
}
// byte offset in a [rows x 64 halves] tile, XOR-swizzled 16B chunks per row
__device__ __forceinline__ uint32_t swb(int row, int col /*halves*/) {
    return (uint32_t)(row * 128) + ((((col >> 3) ^ (row & 7)) << 4) | ((col & 7) * 2));
}
__device__ __forceinline__ uint32_t smem_u32(const void* p) {
    uint32_t a;
    asm("{ .reg .u64 t; cvta.to.shared.u64 t, %1; cvt.u32.u64 %0, t; }" : "=r"(a) : "l"(p));
    return a;
}
__device__ __forceinline__ void ldsm4(uint32_t* r, uint32_t a) {
    asm volatile("ldmatrix.sync.aligned.m8n8.x4.shared.b16 {%0,%1,%2,%3}, [%4];"
        : "=r"(r[0]), "=r"(r[1]), "=r"(r[2]), "=r"(r[3]) : "r"(a));
}
__device__ __forceinline__ void mma16816(float* c, const uint32_t* a, const uint32_t* b) {
    asm volatile(
        "mma.sync.aligned.m16n8k16.row.col.f32.bf16.bf16.f32 "
        "{%0,%1,%2,%3}, {%4,%5,%6,%7}, {%8,%9}, {%0,%1,%2,%3};"
        : "+f"(c[0]), "+f"(c[1]), "+f"(c[2]), "+f"(c[3])
        : "r"(a[0]), "r"(a[1]), "r"(a[2]), "r"(a[3]), "r"(b[0]), "r"(b[1]));
}

// ---------------- prep: weights -> bf16 hi/lo [N,K]; PE table --------------
__global__ void k_prep(const float* __restrict__ conv_w, const float* __restrict__ Wq,
                       const float* __restrict__ Wo, const float* __restrict__ W1,
                       const float* __restrict__ W2) {
    int idx = blockIdx.x * 256 + threadIdx.x;   // 65536 total
    __nv_bfloat16 h, l;
    if (idx < 49152) {   // conv: N=128 (dout), K=384 (s*128+din)
        int n = idx / 384, k = idx - n*384;
        int s = k >> 7, din = k & 127;
        fsplit(conv_w[n*384 + din*3 + s], h, l);
        g_cw_h[idx] = h; g_cw_l[idx] = l;
    }
    {   // forward DFT basis: N=128 (coeff), K=512 (t)
        int n = idx >> 9, t = idx & 511, m = n & 63;
        float x = (float)(m * t) * (1.0f/256.0f);
        float v = (n < 64) ? cospif(x) : -sinpif(x);
        fsplit(v, h, l); g_fb_h[idx] = h; g_fb_l[idx] = l;
    }
    {   // inverse DFT basis: N=512 (t), K=128 (coeff)
        int t = idx >> 7, n = idx & 127, m = n & 63;
        float x = (float)(m * t) * (1.0f/256.0f);
        float v;
        if (n == 0)       v = 1.0f/512.0f;
        else if (n < 64)  v = cospif(x) * (2.0f/512.0f);
        else if (n == 64) v = 0.0f;
        else              v = -sinpif(x) * (2.0f/512.0f);
        fsplit(v, h, l); g_ib_h[idx] = h; g_ib_l[idx] = l;
    }
    #pragma unroll
    for (int ly = 0; ly < 2; ly++) {
        if (idx < 16384) {
            int n = idx >> 7, k = idx & 127;
            fsplit(Wq[ly*16384 + k*128 + n], h, l);
            g_wq_h[ly*16384 + idx] = h; g_wq_l[ly*16384 + idx] = l;
            fsplit(Wo[ly*16384 + k*128 + n], h, l);
            g_wo_h[ly*16384 + idx] = h; g_wo_l[ly*16384 + idx] = l;
        }
        {   // W1: N=512, K=128
            int n = idx >> 7, k = idx & 127;
            fsplit(W1[ly*65536 + k*512 + n], h, l);
            g_w1_h[ly*65536 + idx] = h; g_w1_l[ly*65536 + idx] = l;
        }
        {   // W2: N=128, K=512
            int n = idx >> 9, k = idx & 511;
            fsplit(W2[ly*65536 + k*128 + n], h, l);
            g_w2_h[ly*65536 + idx] = h; g_w2_l[ly*65536 + idx] = l;
        }
    }
    {   // PE
        int t = idx >> 7, d = idx & 127;
        int i2 = d & ~1;
        float div = expf((float)i2 * (-9.210340371976184f / 128.0f));
        float a = (float)t * div;
        g_PE[idx] = (d & 1) ? cosf(a) : sinf(a);
    }
}

// ---------------- transpose & edges ----------------
__global__ void k_transpose(const float* __restrict__ x_enc,
                            const float* __restrict__ mark) {
    __shared__ float tile [32][33];
    __shared__ float tileM[32][33];
    int b = blockIdx.z;
    int d0 = blockIdx.y * 32, l0 = blockIdx.x * 32;
    int tx = threadIdx.x, ty = threadIdx.y;
    const float* xb = x_enc + b*65536;
    const float* mb = mark  + b*65536;
    #pragma unroll
    for (int i = ty; i < 32; i += 8) {
        tile [i][tx] = xb[(d0+i)*512 + l0 + tx];
        tileM[i][tx] = mb[(d0+i)*512 + l0 + tx];
    }
    __syncthreads();
    float* xo = g_Xtp   + b*LP_*128;
    float* mo = g_MarkT + b*65536;
    #pragma unroll
    for (int i = ty; i < 32; i += 8) {
        xo[(l0+i+1)*128 + d0+tx] = tile [tx][i];
        mo[(l0+i  )*128 + d0+tx] = tileM[tx][i];
    }
}
__global__ void k_edges(const float* __restrict__ x_enc) {
    int idx = blockIdx.x*256 + threadIdx.x;
    if (idx < B_*D_) {
        int b = idx >> 7, d = idx & 127;
        g_Xtp[b*LP_*128 +   0*128 + d] = x_enc[b*65536 + d*512 + 511];
        g_Xtp[b*LP_*128 + 513*128 + d] = x_enc[b*65536 + d*512 +   0];
    }
}

// ---------------- HMMA split-bf16 GEMM --------------------------------------
// C[128x128 tile] = epi( A(row,:) @ B^T ), B = [N,K] bf16 hi/lo.
// A(row,k) = A[(row>>absh)*abstr + (row&mask)*arstr + k*akstr]  (fp32)
// EPI bits: 1=+bias[col], 2=+res[row*ldc+col], 4=gelu, 8=+PE[(row&511)*128+(col&127)]
// SMEM (64KB): Ah@0, Al@16K, Bh@32K, Bl@48K; each 128 rows x 64 halves, swizzled.
template<int LOADA, int EPI>
__global__ void __launch_bounds__(256, 1) k_tgemm(
    const float* __restrict__ A,
    const __nv_bfloat16* __restrict__ Bh, const __nv_bfloat16* __restrict__ Bl,
    const float* __restrict__ bias, const float* __restrict__ res,
    float* __restrict__ C,
    int K, int ldc, int absh, int abstr, int arstr, int akstr)
{
    extern __shared__ char sm[];
    const uint32_t sU = smem_u32(sm);
    const int tid = threadIdx.x, wid = tid >> 5, lane = tid & 31;
    const int rowBase = blockIdx.x * 128, colBase = blockIdx.y * 128;
    const int amask = (1 << absh) - 1;

    float acc[4][4][4];
    #pragma unroll
    for (int i = 0; i < 4; i++)
        #pragma unroll
        for (int j = 0; j < 4; j++)
            #pragma unroll
            for (int q = 0; q < 4; q++) acc[i][j][q] = 0.f;

    float4 pa[8];
    float  pas[32];
    uint4  pbh[4], pbl[4];
    const int nc = K >> 6;

    // ---- GLD chunk 0 ----
    {
        const int k0 = 0;
        if (LOADA == 0) {
            #pragma unroll
            for (int i = 0; i < 8; i++) {
                int v = i*256 + tid, row = v >> 4, c4 = (v & 15) * 4;
                int rg = rowBase + row;
                int base = (rg >> absh)*abstr + (rg & amask)*arstr;
                pa[i] = *(const float4*)(A + base + k0 + c4);
            }
        } else {
            #pragma unroll
            for (int i = 0; i < 32; i++) {
                int e = i*256 + tid, row = e & 127, k = e >> 7;
                int rg = rowBase + row;
                int base = (rg >> absh)*abstr + (rg & amask)*arstr;
                pas[i] = A[base + (k0 + k)*akstr];
            }
        }
        #pragma unroll
        for (int i = 0; i < 4; i++) {
            int v = i*256 + tid, n = v >> 3, c8 = (v & 7) * 8;
            long gi = (long)(colBase + n) * K + k0 + c8;
            pbh[i] = *(const uint4*)(Bh + gi);
            pbl[i] = *(const uint4*)(Bl + gi);
        }
    }

    const int mrow = (wid >> 2) * 64;
    const int ncol = (wid & 3) * 32;

    for (int c = 0; c < nc; c++) {
        // ---- STS from prefetch regs ----
        if (LOADA == 0) {
            #pragma unroll
            for (int i = 0; i < 8; i++) {
                int v = i*256 + tid, row = v >> 4, c4 = (v & 15) * 4;
                __nv_bfloat16 h0,h1,h2,h3,l0,l1,l2,l3;
                fsplit(pa[i].x,h0,l0); fsplit(pa[i].y,h1,l1);
                fsplit(pa[i].z,h2,l2); fsplit(pa[i].w,h3,l3);
                uint32_t ad = swb(row, c4);
                *(uint2*)(sm + ad)         = make_uint2(pack2(h0,h1), pack2(h2,h3));
                *(uint2*)(sm + 16384 + ad) = make_uint2(pack2(l0,l1), pack2(l2,l3));
            }
        } else {
            #pragma unroll
            for (int i = 0; i < 32; i++) {
                int e = i*256 + tid, row = e & 127, k = e >> 7;
                __nv_bfloat16 h, l; fsplit(pas[i], h, l);
                uint32_t ad = swb(row, k);
                *(__nv_bfloat16*)(sm + ad)         = h;
                *(__nv_bfloat16*)(sm + 16384 + ad) = l;
            }
        }
        #pragma unroll
        for (int i = 0; i < 4; i++) {
            int v = i*256 + tid, n = v >> 3, c8 = (v & 7) * 8;
            uint32_t ad = swb(n, c8);
            *(uint4*)(sm + 32768 + ad) = pbh[i];
            *(uint4*)(sm + 49152 + ad) = pbl[i];
        }
        __syncthreads();

        // ---- GLD chunk c+1 (hidden under MMA) ----
        if (c + 1 < nc) {
            const int k0 = (c + 1) << 6;
            if (LOADA == 0) {
                #pragma unroll
                for (int i = 0; i < 8; i++) {
                    int v = i*256 + tid, row = v >> 4, c4 = (v & 15) * 4;
                    int rg = rowBase + row;
                    int base = (rg >> absh)*abstr + (rg & amask)*arstr;
                    pa[i] = *(const float4*)(A + base + k0 + c4);
                }
            } else {
                #pragma unroll
                for (int i = 0; i < 32; i++) {
                    int e = i*256 + tid, row = e & 127, k = e >> 7;
                    int rg = rowBase + row;
                    int base = (rg >> absh)*abstr + (rg & amask)*arstr;
                    pas[i] = A[base + (k0 + k)*akstr];
                }
            }
            #pragma unroll
            for (int i = 0; i < 4; i++) {
                int v = i*256 + tid, n = v >> 3, c8 = (v & 7) * 8;
                long gi = (long)(colBase + n) * K + k0 + c8;
                pbh[i] = *(const uint4*)(Bh + gi);
                pbl[i] = *(const uint4*)(Bl + gi);
            }
        }

        // ---- MMA on this chunk ----
        #pragma unroll
        for (int ks = 0; ks < 4; ks++) {
            const int kc = ks * 2;
            uint32_t af[4][4], bhf[2][4], blf[2][4];
            // B-hi frags: 2x ldmatrix.x4 -> 4 n-frags of 8 cols
            #pragma unroll
            for (int g = 0; g < 2; g++) {
                int r  = ncol + g*16 + (lane & 7) + ((lane & 16) ? 8 : 0);
                int ch = kc + ((lane >> 3) & 1);
                ldsm4(bhf[g], sU + 32768 + (uint32_t)(r*128) + (((ch ^ (r & 7)) << 4)));
            }
            // A-hi frags
            #pragma unroll
            for (int mi = 0; mi < 4; mi++) {
                int r  = mrow + mi*16 + (lane & 15);
                int ch = kc + (lane >> 4);
                ldsm4(af[mi], sU + (uint32_t)(r*128) + (((ch ^ (r & 7)) << 4)));
            }
            #pragma unroll
            for (int mi = 0; mi < 4; mi++)
                #pragma unroll
                for (int ni = 0; ni < 4; ni++)
                    mma16816(acc[mi][ni], af[mi], &bhf[ni >> 1][(ni & 1) * 2]);
            // B-lo frags, Ah x Bl
            #pragma unroll
            for (int g = 0; g < 2; g++) {
                int r  = ncol + g*16 + (lane & 7) + ((lane & 16) ? 8 : 0);
                int ch = kc + ((lane >> 3) & 1);
                ldsm4(blf[g], sU + 49152 + (uint32_t)(r*128) + (((ch ^ (r & 7)) << 4)));
            }
            #pragma unroll
            for (int mi = 0; mi < 4; mi++)
                #pragma unroll
                for (int ni = 0; ni < 4; ni++)
                    mma16816(acc[mi][ni], af[mi], &blf[ni >> 1][(ni & 1) * 2]);
            // A-lo frags (reuse af), Al x Bh
            #pragma unroll
            for (int mi = 0; mi < 4; mi++) {
                int r  = mrow + mi*16 + (lane & 15);
                int ch = kc + (lane >> 4);
                ldsm4(af[mi], sU + 16384 + (uint32_t)(r*128) + (((ch ^ (r & 7)) << 4)));
            }
            #pragma unroll
            for (int mi = 0; mi < 4; mi++)
                #pragma unroll
                for (int ni = 0; ni < 4; ni++)
                    mma16816(acc[mi][ni], af[mi], &bhf[ni >> 1][(ni & 1) * 2]);
        }
        __syncthreads();
    }

    // ---- epilogue ----
    #pragma unroll
    for (int mi = 0; mi < 4; mi++) {
        #pragma unroll
        for (int half = 0; half < 2; half++) {
            int grow = rowBase + mrow + mi*16 + (lane >> 2) + half*8;
            #pragma unroll
            for (int ni = 0; ni < 4; ni++) {
                int gcol = colBase + ncol + ni*8 + (lane & 3)*2;
                float v0 = acc[mi][ni][half*2 + 0];
                float v1 = acc[mi][ni][half*2 + 1];
                if (EPI & 1) { v0 += bias[gcol]; v1 += bias[gcol + 1]; }
                if (EPI & 8) {
                    int pbi = (grow & 511)*128 + (gcol & 127);
                    v0 += g_PE[pbi]; v1 += g_PE[pbi + 1];
                }
                long oidx = (long)grow * ldc + gcol;
                if (EPI & 2) {
                    float2 rr = *(const float2*)(res + oidx);
                    v0 += rr.x; v1 += rr.y;
                }
                if (EPI & 4) { v0 = geluf(v0); v1 = geluf(v1); }
                float2 o; o.x = v0; o.y = v1;
                *(float2*)(C + oidx) = o;
            }
        }
    }
}

// ---------------- complex mode mixing ----------------
__global__ void k_mix(const float* __restrict__ fwr,
                      const float* __restrict__ fwi, int layer) {
    int b = blockIdx.x, hh = blockIdx.y;
    int m = threadIdx.x;
    const float* wr = fwr + (size_t)((layer*H_ + hh)*E_*E_) * 64;
    const float* wi = fwi + (size_t)((layer*H_ + hh)*E_*E_) * 64;
    float sr[E_], si[E_];
    #pragma unroll
    for (int o = 0; o < E_; o++) { sr[o] = 0.f; si[o] = 0.f; }
    const float* Fb = g_F + (b*128 + hh*16) * 128;
    #pragma unroll
    for (int e = 0; e < E_; e++) {
        float fre = Fb[e*128 + m];
        float fim = Fb[e*128 + 64 + m];
        #pragma unroll
        for (int o = 0; o < E_; o++) {
            float cr = wr[(e*E_ + o)*64 + m];
            float ci = wi[(e*E_ + o)*64 + m];
            sr[o] += fre*cr - fim*ci;
            si[o] += fre*ci + fim*cr;
        }
    }
    float* Sb = g_SEL + (b*128 + hh*16) * 128;
    #pragma unroll
    for (int o = 0; o < E_; o++) {
        Sb[o*128 + m]      = sr[o];
        Sb[o*128 + 64 + m] = si[o];
    }
}

// ---------------- series_decomp ----------------
__global__ void k_movsub(const float* __restrict__ X, float* __restrict__ Out) {
    __shared__ float sh[88 * 128];
    int b = blockIdx.x, t0 = blockIdx.y * 64;
    int d = threadIdx.x;
    const float* Xb = X + b*65536;
    #pragma unroll 4
    for (int r = 0; r < 88; r++) {
        int t = t0 + r - 12;
        t = max(0, min(511, t));
        sh[r*128 + d] = Xb[t*128 + d];
    }
    float s = 0.f;
    #pragma unroll 4
    for (int r = 0; r < 88; r++) { s += sh[r*128 + d]; sh[r*128 + d] = s; }
    float* Ob = Out + b*65536;
    #pragma unroll 4
    for (int tt = 0; tt < 64; tt++) {
        int r = tt + 12;
        float hi = sh[(r+12)*128 + d];
        float lo = (r >= 13) ? sh[(r-13)*128 + d] : 0.f;
        Ob[(t0+tt)*128 + d] = Xb[(t0+tt)*128 + d] - (hi - lo) * (1.0f/25.0f);
    }
}

// ---------------- LayerNorm ----------------
__global__ void k_ln(const float* __restrict__ X, const float* __restrict__ g,
                     const float* __restrict__ be, float* __restrict__ Out) {
    int row  = blockIdx.x*8 + (threadIdx.x >> 5);
    int lane = threadIdx.x & 31;
    const float* xr = X + (size_t)row * 128;
    float v[4];
    float s = 0.f;
    #pragma unroll
    for (int i = 0; i < 4; i++) { v[i] = xr[lane + i*32]; s += v[i]; }
    #pragma unroll
    for (int o = 16; o > 0; o >>= 1) s += __shfl_xor_sync(0xffffffffu, s, o);
    float mu = s * (1.0f/128.0f);
    float q = 0.f;
    #pragma unroll
    for (int i = 0; i < 4; i++) { float dl = v[i] - mu; q += dl*dl; }
    #pragma unroll
    for (int o = 16; o > 0; o >>= 1) q += __shfl_xor_sync(0xffffffffu, q, o);
    float rstd = rsqrtf(q * (1.0f/128.0f) + 1e-5f);
    float* orow = Out + (size_t)row * 128;
    #pragma unroll
    for (int i = 0; i < 4; i++) {
        int d = lane + i*32;
        orow[d] = (v[i] - mu) * rstd * g[d] + be[d];
    }
}

__global__ void k_zero(float* p, int n) {
    int i = blockIdx.x*256 + threadIdx.x;
    if (i < n) p[i] = 0.f;
}
__global__ void k_colmean(const float* __restrict__ HN) {
    int b = blockIdx.x, t0 = blockIdx.y * 64, d = threadIdx.x;
    const float* Xb = HN + b*65536;
    float s = 0.f;
    #pragma unroll 8
    for (int tt = 0; tt < 64; tt++) s += Xb[(t0+tt)*128 + d];
    atomicAdd(&g_CM[b*128 + d], s);
}
__global__ void k_final(const float* __restrict__ HN, const float* __restrict__ pw,
                        const float* __restrict__ pb, float* __restrict__ out) {
    int b = blockIdx.x, tid = threadIdx.x;
    const float* hb = HN + b*65536;
    const float* mb = g_MarkT + b*65536;
    float s = 0.f;
    for (int i = tid; i < 65536; i += 256) {
        float v = hb[i] - g_CM[b*128 + (i & 127)] * (1.0f/512.0f);
        s += geluf(v) * mb[i] * pw[i];
    }
    __shared__ float red[256];
    red[tid] = s; __syncthreads();
    #pragma unroll
    for (int o = 128; o > 0; o >>= 1) {
        if (tid < o) red[tid] += red[tid + o];
        __syncthreads();
    }
    if (tid == 0) out[b] = red[0] + pb[0];
}

// ---------------- host orchestration ----------------
#define SMB 65536

extern "C" void kernel_launch(void* const* d_in, const int* in_sizes, int n_in,
                              void* d_out, int out_size) {
    const float* x_enc  = (const float*)d_in[0];
    const float* mark   = (const float*)d_in[1];
    const float* conv_w = (const float*)d_in[4];
    const float* Wq     = (const float*)d_in[5];
    const float* bq     = (const float*)d_in[6];
    const float* Wo     = (const float*)d_in[7];
    const float* bo     = (const float*)d_in[8];
    const float* fwr    = (const float*)d_in[9];
    const float* fwi    = (const float*)d_in[10];
    const float* W1     = (const float*)d_in[11];
    const float* W2     = (const float*)d_in[12];
    const float* ln_g   = (const float*)d_in[13];
    const float* ln_b   = (const float*)d_in[14];
    const float* pw     = (const float*)d_in[15];
    const float* pb     = (const float*)d_in[16];
    float* out = (float*)d_out;

    cudaFuncSetAttribute(k_tgemm<0,8>, cudaFuncAttributeMaxDynamicSharedMemorySize, SMB);
    cudaFuncSetAttribute(k_tgemm<0,1>, cudaFuncAttributeMaxDynamicSharedMemorySize, SMB);
    cudaFuncSetAttribute(k_tgemm<1,0>, cudaFuncAttributeMaxDynamicSharedMemorySize, SMB);
    cudaFuncSetAttribute(k_tgemm<0,0>, cudaFuncAttributeMaxDynamicSharedMemorySize, SMB);
    cudaFuncSetAttribute(k_tgemm<0,3>, cudaFuncAttributeMaxDynamicSharedMemorySize, SMB);
    cudaFuncSetAttribute(k_tgemm<0,4>, cudaFuncAttributeMaxDynamicSharedMemorySize, SMB);
    cudaFuncSetAttribute(k_tgemm<0,2>, cudaFuncAttributeMaxDynamicSharedMemorySize, SMB);

    float *pXtp, *pH, *pT1, *pT2, *pU, *pF, *pSEL, *pCM;
    cudaGetSymbolAddress((void**)&pXtp, g_Xtp);
    cudaGetSymbolAddress((void**)&pH,   g_H);
    cudaGetSymbolAddress((void**)&pT1,  g_T1);
    cudaGetSymbolAddress((void**)&pT2,  g_T2);
    cudaGetSymbolAddress((void**)&pU,   g_U);
    cudaGetSymbolAddress((void**)&pF,   g_F);
    cudaGetSymbolAddress((void**)&pSEL, g_SEL);
    cudaGetSymbolAddress((void**)&pCM,  g_CM);
    __nv_bfloat16 *cwh,*cwl,*fbh,*fbl,*ibh,*ibl,*wqh,*wql,*woh,*wol,*w1h,*w1l,*w2h,*w2l;
    cudaGetSymbolAddress((void**)&cwh, g_cw_h); cudaGetSymbolAddress((void**)&cwl, g_cw_l);
    cudaGetSymbolAddress((void**)&fbh, g_fb_h); cudaGetSymbolAddress((void**)&fbl, g_fb_l);
    cudaGetSymbolAddress((void**)&ibh, g_ib_h); cudaGetSymbolAddress((void**)&ibl, g_ib_l);
    cudaGetSymbolAddress((void**)&wqh, g_wq_h); cudaGetSymbolAddress((void**)&wql, g_wq_l);
    cudaGetSymbolAddress((void**)&woh, g_wo_h); cudaGetSymbolAddress((void**)&wol, g_wo_l);
    cudaGetSymbolAddress((void**)&w1h, g_w1_h); cudaGetSymbolAddress((void**)&w1l, g_w1_l);
    cudaGetSymbolAddress((void**)&w2h, g_w2_h); cudaGetSymbolAddress((void**)&w2l, g_w2_l);

    k_prep<<<256, 256>>>(conv_w, Wq, Wo, W1, W2);
    k_transpose<<<dim3(16,4,128), dim3(32,8)>>>(x_enc, mark);
    k_edges<<<64, 256>>>(x_enc);

    // TokenEmbedding conv (K=384) + PE
    k_tgemm<0,8><<<dim3(512,1), 256, SMB>>>(
        pXtp, cwh, cwl, nullptr, nullptr, pH, 384, 128, 9, LP_*128, 128, 1);

    for (int l = 0; l < 2; l++) {
        // Q = h @ Wq + bq
        k_tgemm<0,1><<<dim3(512,1), 256, SMB>>>(
            pH, wqh + l*16384, wql + l*16384, bq + l*128, nullptr, pT1,
            128, 128, 30, 0, 128, 1);
        // forward DFT (gathered A)
        k_tgemm<1,0><<<dim3(128,1), 256, SMB>>>(
            pT1, fbh, fbl, nullptr, nullptr, pF, 512, 128, 7, 65536, 1, 128);
        // complex mode mixing
        k_mix<<<dim3(128,8), 64>>>(fwr, fwi, l);
        // inverse DFT; flat layout == scrambled .view(B,L,-1)
        k_tgemm<0,0><<<dim3(128,4), 256, SMB>>>(
            pSEL, ibh, ibl, nullptr, nullptr, pT1, 128, 512, 30, 0, 128, 1);
        // out proj + bias + residual
        k_tgemm<0,3><<<dim3(512,1), 256, SMB>>>(
            pT1, woh + l*16384, wol + l*16384, bo + l*128, pH, pT2,
            128, 128, 30, 0, 128, 1);
        // decomp1
        k_movsub<<<dim3(128,8), 128>>>(pT2, pH);
        // FFN up + gelu
        k_tgemm<0,4><<<dim3(512,4), 256, SMB>>>(
            pH, w1h + l*65536, w1l + l*65536, nullptr, nullptr, pU,
            128, 512, 30, 0, 128, 1);
        // FFN down + residual
        k_tgemm<0,2><<<dim3(512,1), 256, SMB>>>(
            pU, w2h + l*65536, w2l + l*65536, nullptr, pH, pT2,
            512, 128, 30, 0, 512, 1);
        // decomp2
        k_movsub<<<dim3(128,8), 128>>>(pT2, pH);
    }

    k_ln<<<8192, 256>>>(pH, ln_g, ln_b, pT1);
    k_zero<<<64, 256>>>(pCM, B_*D_);
    k_colmean<<<dim3(128,8), 128>>>(pT1);
    k_final<<<128, 256>>>(pT1, pw, pb, out);
}

// round 4
// speedup vs baseline: 1.8486x; 1.0982x over previous
#include <cuda_runtime.h>
#include <cuda_bf16.h>
#include <math.h>
#include <stdint.h>

#define B_    128
#define L_    512
#define D_    128
#define H_    8
#define E_    16
#define DFF_  512
#define LP_   514

// ---------------- fp32 scratch ----------------
__device__ float g_MarkT[B_*L_*D_];
__device__ float g_H    [B_*L_*D_];
__device__ float g_T1   [B_*L_*D_];
__device__ float g_T2   [B_*L_*D_];
__device__ float g_F    [B_*D_*128];
__device__ float g_PE   [512*128];
__device__ float g_CM   [B_*D_];

// ---------------- bf16 hi/lo activation scratch ----------------
__device__ __nv_bfloat16 g_Xh[B_*LP_*D_], g_Xl[B_*LP_*D_];     // conv input
__device__ __nv_bfloat16 g_Hh[B_*L_*D_],  g_Hl[B_*L_*D_];      // hidden
__device__ __nv_bfloat16 g_Qh[B_*L_*D_],  g_Ql[B_*L_*D_];      // Wq out / iDFT out (flat)
__device__ __nv_bfloat16 g_QTh[B_*L_*D_], g_QTl[B_*L_*D_];     // Q transposed (b,d,l)
__device__ __nv_bfloat16 g_Sh[B_*D_*128], g_Sl[B_*D_*128];     // mixed coeffs
__device__ __nv_bfloat16 g_Uh[B_*L_*DFF_], g_Ul[B_*L_*DFF_];   // FFN hidden

// ---------------- bf16 weights (hi/lo split), [N, K] row-major -------------
__device__ __nv_bfloat16 g_cw_h[128*384], g_cw_l[128*384];
__device__ __nv_bfloat16 g_fb_h[128*512], g_fb_l[128*512];
__device__ __nv_bfloat16 g_ib_h[512*128], g_ib_l[512*128];
__device__ __nv_bfloat16 g_wq_h[2*128*128], g_wq_l[2*128*128];
__device__ __nv_bfloat16 g_wo_h[2*128*128], g_wo_l[2*128*128];
__device__ __nv_bfloat16 g_w1_h[2*512*128], g_w1_l[2*512*128];
__device__ __nv_bfloat16 g_w2_h[2*128*512], g_w2_l[2*128*512];

__device__ __forceinline__ float geluf(float v) {
    return 0.5f * v * (1.0f + erff(v * 0.7071067811865476f));
}
__device__ __forceinline__ void fsplit(float x, __nv_bfloat16& h, __nv_bfloat16& l) {
    h = __float2bfloat16_rn(x);
    l = __float2bfloat16_rn(x - __bfloat162float(h));
}
__device__ __forceinline__ uint32_t pack2(__nv_bfloat16 a, __nv_bfloat16 b) {
    return (uint32_t)__bfloat16_as_ushort(a) | ((uint32_t)__bfloat16_as_ushort(b) << 16);
}
__device__ __forceinline__ uint32_t smem_u32(const void* p) {
    uint32_t a;
    asm("{ .reg .u64 t; cvta.to.shared.u64 t, %1; cvt.u32.u64 %0, t; }" : "=r"(a) : "l"(p));
    return a;
}
__device__ __forceinline__ void ldsm4(uint32_t* r, uint32_t a) {
    asm volatile("ldmatrix.sync.aligned.m8n8.x4.shared.b16 {%0,%1,%2,%3}, [%4];"
        : "=r"(r[0]), "=r"(r[1]), "=r"(r[2]), "=r"(r[3]) : "r"(a));
}
__device__ __forceinline__ void mma16816(float* c, const uint32_t* a, const uint32_t* b) {
    asm volatile(
        "mma.sync.aligned.m16n8k16.row.col.f32.bf16.bf16.f32 "
        "{%0,%1,%2,%3}, {%4,%5,%6,%7}, {%8,%9}, {%0,%1,%2,%3};"
        : "+f"(c[0]), "+f"(c[1]), "+f"(c[2]), "+f"(c[3])
        : "r"(a[0]), "r"(a[1]), "r"(a[2]), "r"(a[3]), "r"(b[0]), "r"(b[1]));
}
#define CP16(d, s)   asm volatile("cp.async.cg.shared.global [%0], [%1], 16;" :: "r"(d), "l"(s))
#define CPCOMMIT()   asm volatile("cp.async.commit_group;" ::: "memory")
#define CPWAIT1()    asm volatile("cp.async.wait_group 1;" ::: "memory")

// tile row = 32 halves = 64B = 4x16B chunks; swizzle chunk ^= (row>>1)&3
__device__ __forceinline__ uint32_t sw32(int row, int ch) {
    return (uint32_t)(row * 64) + (uint32_t)(((ch ^ ((row >> 1) & 3)) << 4));
}

// ---------------- prep: weights -> bf16 hi/lo [N,K]; PE table --------------
__global__ void k_prep(const float* __restrict__ conv_w, const float* __restrict__ Wq,
                       const float* __restrict__ Wo, const float* __restrict__ W1,
                       const float* __restrict__ W2) {
    int idx = blockIdx.x * 256 + threadIdx.x;   // 65536 total
    __nv_bfloat16 h, l;
    if (idx < 49152) {   // conv: N=128 (dout), K=384 (s*128+din)
        int n = idx / 384, k = idx - n*384;
        int s = k >> 7, din = k & 127;
        fsplit(conv_w[n*384 + din*3 + s], h, l);
        g_cw_h[idx] = h; g_cw_l[idx] = l;
    }
    {   // forward DFT basis: N=128 (coeff), K=512 (t)
        int n = idx >> 9, t = idx & 511, m = n & 63;
        float x = (float)(m * t) * (1.0f/256.0f);
        float v = (n < 64) ? cospif(x) : -sinpif(x);
        fsplit(v, h, l); g_fb_h[idx] = h; g_fb_l[idx] = l;
    }
    {   // inverse DFT basis: N=512 (t), K=128 (coeff)
        int t = idx >> 7, n = idx & 127, m = n & 63;
        float x = (float)(m * t) * (1.0f/256.0f);
        float v;
        if (n == 0)       v = 1.0f/512.0f;
        else if (n < 64)  v = cospif(x) * (2.0f/512.0f);
        else if (n == 64) v = 0.0f;
        else              v = -sinpif(x) * (2.0f/512.0f);
        fsplit(v, h, l); g_ib_h[idx] = h; g_ib_l[idx] = l;
    }
    #pragma unroll
    for (int ly = 0; ly < 2; ly++) {
        if (idx < 16384) {
            int n = idx >> 7, k = idx & 127;
            fsplit(Wq[ly*16384 + k*128 + n], h, l);
            g_wq_h[ly*16384 + idx] = h; g_wq_l[ly*16384 + idx] = l;
            fsplit(Wo[ly*16384 + k*128 + n], h, l);
            g_wo_h[ly*16384 + idx] = h; g_wo_l[ly*16384 + idx] = l;
        }
        {   // W1: N=512, K=128
            int n = idx >> 7, k = idx & 127;
            fsplit(W1[ly*65536 + k*512 + n], h, l);
            g_w1_h[ly*65536 + idx] = h; g_w1_l[ly*65536 + idx] = l;
        }
        {   // W2: N=128, K=512
            int n = idx >> 9, k = idx & 511;
            fsplit(W2[ly*65536 + k*128 + n], h, l);
            g_w2_h[ly*65536 + idx] = h; g_w2_l[ly*65536 + idx] = l;
        }
    }
    {   // PE
        int t = idx >> 7, d = idx & 127;
        int i2 = d & ~1;
        float div = expf((float)i2 * (-9.210340371976184f / 128.0f));
        float a = (float)t * div;
        g_PE[idx] = (d & 1) ? cosf(a) : sinf(a);
    }
}

// ---------------- input transpose: fp32 (B,D,L) -> bf16 pair (B,L+2,D) -----
__global__ void k_transpose(const float* __restrict__ x_enc,
                            const float* __restrict__ mark) {
    __shared__ float tile [32][33];
    __shared__ float tileM[32][33];
    int b = blockIdx.z;
    int d0 = blockIdx.y * 32, l0 = blockIdx.x * 32;
    int tx = threadIdx.x, ty = threadIdx.y;
    const float* xb = x_enc + b*65536;
    const float* mb = mark  + b*65536;
    #pragma unroll
    for (int i = ty; i < 32; i += 8) {
        tile [i][tx] = xb[(d0+i)*512 + l0 + tx];
        tileM[i][tx] = mb[(d0+i)*512 + l0 + tx];
    }
    __syncthreads();
    float* mo = g_MarkT + b*65536;
    #pragma unroll
    for (int i = ty; i < 32; i += 8) {
        int oi = b*LP_*128 + (l0+i+1)*128 + d0+tx;
        __nv_bfloat16 h, l; fsplit(tile[tx][i], h, l);
        g_Xh[oi] = h; g_Xl[oi] = l;
        mo[(l0+i)*128 + d0+tx] = tileM[tx][i];
    }
}
__global__ void k_edges(const float* __restrict__ x_enc) {
    int idx = blockIdx.x*256 + threadIdx.x;
    if (idx < B_*D_) {
        int b = idx >> 7, d = idx & 127;
        __nv_bfloat16 h, l;
        fsplit(x_enc[b*65536 + d*512 + 511], h, l);
        g_Xh[b*LP_*128 + d] = h; g_Xl[b*LP_*128 + d] = l;
        fsplit(x_enc[b*65536 + d*512], h, l);
        g_Xh[b*LP_*128 + 513*128 + d] = h; g_Xl[b*LP_*128 + 513*128 + d] = l;
    }
}

// ---------------- bf16 pair transpose (b,l,d) -> (b,d,l) ----------------
__global__ void k_tq() {
    __shared__ __nv_bfloat16 th[32][34], tl[32][34];
    int b = blockIdx.z;
    int l0 = blockIdx.x * 32, d0 = blockIdx.y * 32;
    int tx = threadIdx.x, ty = threadIdx.y;
    #pragma unroll
    for (int i = ty; i < 32; i += 8) {
        int gi = b*65536 + (l0+i)*128 + d0 + tx;
        th[i][tx] = g_Qh[gi]; tl[i][tx] = g_Ql[gi];
    }
    __syncthreads();
    #pragma unroll
    for (int i = ty; i < 32; i += 8) {
        int go = b*65536 + (d0+i)*512 + l0 + tx;
        g_QTh[go] = th[tx][i]; g_QTl[go] = tl[tx][i];
    }
}

// ---------------- HMMA split-bf16 GEMM, cp.async 3-stage --------------------
// C[128x128 tile] = epi( A(row,:) @ B^T ); A,B bf16 hi/lo; K-chunk 32.
// A(row,k) = Ax[(row>>absh)*abstr + (row&mask)*arstr + k]
// EPI bits: 1=+bias[col], 2=+res, 4=gelu, 8=+PE, 16=skip fp32 C store
// WRB: also write bf16 hi/lo result to Ch/Cl (same flat index)
// SMEM per stage (32KB): Ah@0 Al@8K Bh@16K Bl@24K; 3 stages = 96KB.
template<int EPI, int WRB>
__global__ void __launch_bounds__(256, 2) k_tgemm(
    const __nv_bfloat16* __restrict__ Ah, const __nv_bfloat16* __restrict__ Al,
    const __nv_bfloat16* __restrict__ Bh, const __nv_bfloat16* __restrict__ Bl,
    const float* __restrict__ bias, const float* __restrict__ res,
    float* __restrict__ C, __nv_bfloat16* __restrict__ Ch, __nv_bfloat16* __restrict__ Cl,
    int K, int ldc, int absh, int abstr, int arstr)
{
    extern __shared__ char sm[];
    const uint32_t sU = smem_u32(sm);
    const int tid = threadIdx.x, wid = tid >> 5, lane = tid & 31;
    const int rowBase = blockIdx.x * 128, colBase = blockIdx.y * 128;
    const int amask = (1 << absh) - 1;

    float acc[4][4][4];
    #pragma unroll
    for (int i = 0; i < 4; i++)
        #pragma unroll
        for (int j = 0; j < 4; j++)
            #pragma unroll
            for (int q = 0; q < 4; q++) acc[i][j][q] = 0.f;

    // per-thread load slots: 8 x 16B pieces per chunk
    // p = i*256+tid: tile = p>>9 (0 Ah,1 Al,2 Bh,3 Bl), row=(p>>2)&127, ch=p&3
    const int nc = K >> 5;

    auto load_chunk = [&](int stage, int k0) {
        uint32_t sb = sU + stage * 32768;
        #pragma unroll
        for (int i = 0; i < 8; i++) {
            int p = i*256 + tid;
            int t4 = p >> 9, row = (p >> 2) & 127, ch = p & 3;
            uint32_t dst = sb + t4*8192 + sw32(row, ch);
            const __nv_bfloat16* src;
            if (t4 < 2) {
                int rg = rowBase + row;
                int base = (rg >> absh)*abstr + (rg & amask)*arstr;
                src = (t4 == 0 ? Ah : Al) + base + k0 + ch*8;
            } else {
                src = (t4 == 2 ? Bh : Bl) + (long)(colBase + row)*K + k0 + ch*8;
            }
            CP16(dst, src);
        }
    };

    load_chunk(0, 0);  CPCOMMIT();
    load_chunk(1, 32); CPCOMMIT();

    const int mrow = (wid >> 2) * 64;
    const int ncol = (wid & 3) * 32;
    int stage = 0;

    for (int c = 0; c < nc; c++) {
        CPWAIT1();
        __syncthreads();
        if (c + 2 < nc) {
            int ns = stage + 2; if (ns >= 3) ns -= 3;
            load_chunk(ns, (c + 2) * 32);
        }
        CPCOMMIT();

        uint32_t sb = sU + stage * 32768;
        #pragma unroll
        for (int ks = 0; ks < 2; ks++) {
            uint32_t af[4][4], bhf[2][4], blf[2][4];
            #pragma unroll
            for (int g = 0; g < 2; g++) {
                int r  = ncol + g*16 + (lane & 7) + ((lane & 16) ? 8 : 0);
                int ci = ks*2 + ((lane >> 3) & 1);
                ldsm4(bhf[g], sb + 16384 + sw32(r, ci));
            }
            #pragma unroll
            for (int mi = 0; mi < 4; mi++) {
                int r  = mrow + mi*16 + (lane & 15);
                int ci = ks*2 + (lane >> 4);
                ldsm4(af[mi], sb + sw32(r, ci));
            }
            #pragma unroll
            for (int mi = 0; mi < 4; mi++)
                #pragma unroll
                for (int ni = 0; ni < 4; ni++)
                    mma16816(acc[mi][ni], af[mi], &bhf[ni >> 1][(ni & 1) * 2]);
            #pragma unroll
            for (int g = 0; g < 2; g++) {
                int r  = ncol + g*16 + (lane & 7) + ((lane & 16) ? 8 : 0);
                int ci = ks*2 + ((lane >> 3) & 1);
                ldsm4(blf[g], sb + 24576 + sw32(r, ci));
            }
            #pragma unroll
            for (int mi = 0; mi < 4; mi++)
                #pragma unroll
                for (int ni = 0; ni < 4; ni++)
                    mma16816(acc[mi][ni], af[mi], &blf[ni >> 1][(ni & 1) * 2]);
            #pragma unroll
            for (int mi = 0; mi < 4; mi++) {
                int r  = mrow + mi*16 + (lane & 15);
                int ci = ks*2 + (lane >> 4);
                ldsm4(af[mi], sb + 8192 + sw32(r, ci));
            }
            #pragma unroll
            for (int mi = 0; mi < 4; mi++)
                #pragma unroll
                for (int ni = 0; ni < 4; ni++)
                    mma16816(acc[mi][ni], af[mi], &bhf[ni >> 1][(ni & 1) * 2]);
        }
        if (++stage >= 3) stage -= 3;
    }

    // ---- epilogue ----
    #pragma unroll
    for (int mi = 0; mi < 4; mi++) {
        #pragma unroll
        for (int half = 0; half < 2; half++) {
            int grow = rowBase + mrow + mi*16 + (lane >> 2) + half*8;
            #pragma unroll
            for (int ni = 0; ni < 4; ni++) {
                int gcol = colBase + ncol + ni*8 + (lane & 3)*2;
                float v0 = acc[mi][ni][half*2 + 0];
                float v1 = acc[mi][ni][half*2 + 1];
                if (EPI & 1) { v0 += bias[gcol]; v1 += bias[gcol + 1]; }
                if (EPI & 8) {
                    int pbi = (grow & 511)*128 + (gcol & 127);
                    v0 += g_PE[pbi]; v1 += g_PE[pbi + 1];
                }
                long oidx = (long)grow * ldc + gcol;
                if (EPI & 2) {
                    float2 rr = *(const float2*)(res + oidx);
                    v0 += rr.x; v1 += rr.y;
                }
                if (EPI & 4) { v0 = geluf(v0); v1 = geluf(v1); }
                if (!(EPI & 16)) {
                    float2 o; o.x = v0; o.y = v1;
                    *(float2*)(C + oidx) = o;
                }
                if (WRB) {
                    __nv_bfloat16 h0,l0,h1,l1;
                    fsplit(v0,h0,l0); fsplit(v1,h1,l1);
                    *(uint32_t*)(Ch + oidx) = pack2(h0,h1);
                    *(uint32_t*)(Cl + oidx) = pack2(l0,l1);
                }
            }
        }
    }
}

// ---------------- complex mode mixing (fp32 in, bf16 pair out) -------------
__global__ void k_mix(const float* __restrict__ fwr,
                      const float* __restrict__ fwi, int layer) {
    int b = blockIdx.x, hh = blockIdx.y;
    int m = threadIdx.x;
    const float* wr = fwr + (size_t)((layer*H_ + hh)*E_*E_) * 64;
    const float* wi = fwi + (size_t)((layer*H_ + hh)*E_*E_) * 64;
    float sr[E_], si[E_];
    #pragma unroll
    for (int o = 0; o < E_; o++) { sr[o] = 0.f; si[o] = 0.f; }
    const float* Fb = g_F + (b*128 + hh*16) * 128;
    #pragma unroll
    for (int e = 0; e < E_; e++) {
        float fre = Fb[e*128 + m];
        float fim = Fb[e*128 + 64 + m];
        #pragma unroll
        for (int o = 0; o < E_; o++) {
            float cr = wr[(e*E_ + o)*64 + m];
            float ci = wi[(e*E_ + o)*64 + m];
            sr[o] += fre*cr - fim*ci;
            si[o] += fre*ci + fim*cr;
        }
    }
    int base = (b*128 + hh*16) * 128;
    #pragma unroll
    for (int o = 0; o < E_; o++) {
        __nv_bfloat16 h, l;
        fsplit(sr[o], h, l);
        g_Sh[base + o*128 + m] = h;      g_Sl[base + o*128 + m] = l;
        fsplit(si[o], h, l);
        g_Sh[base + o*128 + 64 + m] = h; g_Sl[base + o*128 + 64 + m] = l;
    }
}

// ---------------- series_decomp: fp32 + bf16-pair outputs ------------------
__global__ void k_movsub(const float* __restrict__ X, float* __restrict__ Out,
                         __nv_bfloat16* __restrict__ Oh, __nv_bfloat16* __restrict__ Ol) {
    __shared__ float sh[88 * 128];
    int b = blockIdx.x, t0 = blockIdx.y * 64;
    int d = threadIdx.x;
    const float* Xb = X + b*65536;
    #pragma unroll 4
    for (int r = 0; r < 88; r++) {
        int t = t0 + r - 12;
        t = max(0, min(511, t));
        sh[r*128 + d] = Xb[t*128 + d];
    }
    float s = 0.f;
    #pragma unroll 4
    for (int r = 0; r < 88; r++) { s += sh[r*128 + d]; sh[r*128 + d] = s; }
    #pragma unroll 4
    for (int tt = 0; tt < 64; tt++) {
        int r = tt + 12;
        float hi = sh[(r+12)*128 + d];
        float lo = (r >= 13) ? sh[(r-13)*128 + d] : 0.f;
        float v = Xb[(t0+tt)*128 + d] - (hi - lo) * (1.0f/25.0f);
        int oi = b*65536 + (t0+tt)*128 + d;
        Out[oi] = v;
        __nv_bfloat16 h, l; fsplit(v, h, l);
        Oh[oi] = h; Ol[oi] = l;
    }
}

// ---------------- LayerNorm ----------------
__global__ void k_ln(const float* __restrict__ X, const float* __restrict__ g,
                     const float* __restrict__ be, float* __restrict__ Out) {
    int row  = blockIdx.x*8 + (threadIdx.x >> 5);
    int lane = threadIdx.x & 31;
    const float* xr = X + (size_t)row * 128;
    float v[4];
    float s = 0.f;
    #pragma unroll
    for (int i = 0; i < 4; i++) { v[i] = xr[lane + i*32]; s += v[i]; }
    #pragma unroll
    for (int o = 16; o > 0; o >>= 1) s += __shfl_xor_sync(0xffffffffu, s, o);
    float mu = s * (1.0f/128.0f);
    float q = 0.f;
    #pragma unroll
    for (int i = 0; i < 4; i++) { float dl = v[i] - mu; q += dl*dl; }
    #pragma unroll
    for (int o = 16; o > 0; o >>= 1) q += __shfl_xor_sync(0xffffffffu, q, o);
    float rstd = rsqrtf(q * (1.0f/128.0f) + 1e-5f);
    float* orow = Out + (size_t)row * 128;
    #pragma unroll
    for (int i = 0; i < 4; i++) {
        int d = lane + i*32;
        orow[d] = (v[i] - mu) * rstd * g[d] + be[d];
    }
}

__global__ void k_zero(float* p, int n) {
    int i = blockIdx.x*256 + threadIdx.x;
    if (i < n) p[i] = 0.f;
}
__global__ void k_colmean(const float* __restrict__ HN) {
    int b = blockIdx.x, t0 = blockIdx.y * 64, d = threadIdx.x;
    const float* Xb = HN + b*65536;
    float s = 0.f;
    #pragma unroll 8
    for (int tt = 0; tt < 64; tt++) s += Xb[(t0+tt)*128 + d];
    atomicAdd(&g_CM[b*128 + d], s);
}
__global__ void k_final(const float* __restrict__ HN, const float* __restrict__ pw,
                        const float* __restrict__ pb, float* __restrict__ out) {
    int b = blockIdx.x, tid = threadIdx.x;
    const float* hb = HN + b*65536;
    const float* mb = g_MarkT + b*65536;
    float s = 0.f;
    for (int i = tid; i < 65536; i += 256) {
        float v = hb[i] - g_CM[b*128 + (i & 127)] * (1.0f/512.0f);
        s += geluf(v) * mb[i] * pw[i];
    }
    __shared__ float red[256];
    red[tid] = s; __syncthreads();
    #pragma unroll
    for (int o = 128; o > 0; o >>= 1) {
        if (tid < o) red[tid] += red[tid + o];
        __syncthreads();
    }
    if (tid == 0) out[b] = red[0] + pb[0];
}

// ---------------- host orchestration ----------------
#define SMB 98304

extern "C" void kernel_launch(void* const* d_in, const int* in_sizes, int n_in,
                              void* d_out, int out_size) {
    const float* x_enc  = (const float*)d_in[0];
    const float* mark   = (const float*)d_in[1];
    const float* conv_w = (const float*)d_in[4];
    const float* Wq     = (const float*)d_in[5];
    const float* bq     = (const float*)d_in[6];
    const float* Wo     = (const float*)d_in[7];
    const float* bo     = (const float*)d_in[8];
    const float* fwr    = (const float*)d_in[9];
    const float* fwi    = (const float*)d_in[10];
    const float* W1     = (const float*)d_in[11];
    const float* W2     = (const float*)d_in[12];
    const float* ln_g   = (const float*)d_in[13];
    const float* ln_b   = (const float*)d_in[14];
    const float* pw     = (const float*)d_in[15];
    const float* pb     = (const float*)d_in[16];
    float* out = (float*)d_out;

    cudaFuncSetAttribute(k_tgemm<8,1>,  cudaFuncAttributeMaxDynamicSharedMemorySize, SMB);
    cudaFuncSetAttribute(k_tgemm<17,1>, cudaFuncAttributeMaxDynamicSharedMemorySize, SMB);
    cudaFuncSetAttribute(k_tgemm<0,0>,  cudaFuncAttributeMaxDynamicSharedMemorySize, SMB);
    cudaFuncSetAttribute(k_tgemm<16,1>, cudaFuncAttributeMaxDynamicSharedMemorySize, SMB);
    cudaFuncSetAttribute(k_tgemm<3,0>,  cudaFuncAttributeMaxDynamicSharedMemorySize, SMB);
    cudaFuncSetAttribute(k_tgemm<20,1>, cudaFuncAttributeMaxDynamicSharedMemorySize, SMB);
    cudaFuncSetAttribute(k_tgemm<2,0>,  cudaFuncAttributeMaxDynamicSharedMemorySize, SMB);

    float *pH, *pT1, *pT2, *pF, *pCM;
    cudaGetSymbolAddress((void**)&pH,   g_H);
    cudaGetSymbolAddress((void**)&pT1,  g_T1);
    cudaGetSymbolAddress((void**)&pT2,  g_T2);
    cudaGetSymbolAddress((void**)&pF,   g_F);
    cudaGetSymbolAddress((void**)&pCM,  g_CM);
    __nv_bfloat16 *xh,*xl,*hh,*hl,*qh,*ql,*qth,*qtl,*sh,*sl,*uh,*ul;
    cudaGetSymbolAddress((void**)&xh,  g_Xh);  cudaGetSymbolAddress((void**)&xl,  g_Xl);
    cudaGetSymbolAddress((void**)&hh,  g_Hh);  cudaGetSymbolAddress((void**)&hl,  g_Hl);
    cudaGetSymbolAddress((void**)&qh,  g_Qh);  cudaGetSymbolAddress((void**)&ql,  g_Ql);
    cudaGetSymbolAddress((void**)&qth, g_QTh); cudaGetSymbolAddress((void**)&qtl, g_QTl);
    cudaGetSymbolAddress((void**)&sh,  g_Sh);  cudaGetSymbolAddress((void**)&sl,  g_Sl);
    cudaGetSymbolAddress((void**)&uh,  g_Uh);  cudaGetSymbolAddress((void**)&ul,  g_Ul);
    __nv_bfloat16 *cwh,*cwl,*fbh,*fbl,*ibh,*ibl,*wqh,*wql,*woh,*wol,*w1h,*w1l,*w2h,*w2l;
    cudaGetSymbolAddress((void**)&cwh, g_cw_h); cudaGetSymbolAddress((void**)&cwl, g_cw_l);
    cudaGetSymbolAddress((void**)&fbh, g_fb_h); cudaGetSymbolAddress((void**)&fbl, g_fb_l);
    cudaGetSymbolAddress((void**)&ibh, g_ib_h); cudaGetSymbolAddress((void**)&ibl, g_ib_l);
    cudaGetSymbolAddress((void**)&wqh, g_wq_h); cudaGetSymbolAddress((void**)&wql, g_wq_l);
    cudaGetSymbolAddress((void**)&woh, g_wo_h); cudaGetSymbolAddress((void**)&wol, g_wo_l);
    cudaGetSymbolAddress((void**)&w1h, g_w1_h); cudaGetSymbolAddress((void**)&w1l, g_w1_l);
    cudaGetSymbolAddress((void**)&w2h, g_w2_h); cudaGetSymbolAddress((void**)&w2l, g_w2_l);

    k_prep<<<256, 256>>>(conv_w, Wq, Wo, W1, W2);
    k_transpose<<<dim3(16,4,128), dim3(32,8)>>>(x_enc, mark);
    k_edges<<<64, 256>>>(x_enc);

    // TokenEmbedding conv (K=384) + PE -> fp32 H + bf16 pair H
    k_tgemm<8,1><<<dim3(512,1), 256, SMB>>>(
        xh, xl, cwh, cwl, nullptr, nullptr, pH, hh, hl,
        384, 128, 9, LP_*128, 128);

    for (int l = 0; l < 2; l++) {
        // Q = H @ Wq + bq -> bf16 pair only
        k_tgemm<17,1><<<dim3(512,1), 256, SMB>>>(
            hh, hl, wqh + l*16384, wql + l*16384, bq + l*128, nullptr,
            nullptr, qh, ql, 128, 128, 30, 0, 128);
        // transpose Q (b,l,d) -> (b,d,l)
        k_tq<<<dim3(16,4,128), dim3(32,8)>>>();
        // forward DFT -> fp32 F
        k_tgemm<0,0><<<dim3(128,1), 256, SMB>>>(
            qth, qtl, fbh, fbl, nullptr, nullptr, pF, nullptr, nullptr,
            512, 128, 30, 0, 512);
        // complex mode mixing -> bf16 pair S
        k_mix<<<dim3(128,8), 64>>>(fwr, fwi, l);
        // inverse DFT -> bf16 pair flat (== scrambled view(B,L,-1))
        k_tgemm<16,1><<<dim3(128,4), 256, SMB>>>(
            sh, sl, ibh, ibl, nullptr, nullptr, nullptr, qh, ql,
            128, 512, 30, 0, 128);
        // out proj + bias + residual -> fp32 T2
        k_tgemm<3,0><<<dim3(512,1), 256, SMB>>>(
            qh, ql, woh + l*16384, wol + l*16384, bo + l*128, pH,
            pT2, nullptr, nullptr, 128, 128, 30, 0, 128);
        // decomp1 -> fp32 H + bf16 pair H
        k_movsub<<<dim3(128,8), 128>>>(pT2, pH, hh, hl);
        // FFN up + gelu -> bf16 pair U
        k_tgemm<20,1><<<dim3(512,4), 256, SMB>>>(
            hh, hl, w1h + l*65536, w1l + l*65536, nullptr, nullptr,
            nullptr, uh, ul, 128, 512, 30, 0, 128);
        // FFN down + residual -> fp32 T2
        k_tgemm<2,0><<<dim3(512,1), 256, SMB>>>(
            uh, ul, w2h + l*65536, w2l + l*65536, nullptr, pH,
            pT2, nullptr, nullptr, 512, 128, 30, 0, 512);
        // decomp2 -> fp32 H + bf16 pair H
        k_movsub<<<dim3(128,8), 128>>>(pT2, pH, hh, hl);
    }

    k_ln<<<8192, 256>>>(pH, ln_g, ln_b, pT1);
    k_zero<<<64, 256>>>(pCM, B_*D_);
    k_colmean<<<dim3(128,8), 128>>>(pT1);
    k_final<<<128, 256>>>(pT1, pw, pb, out);
}

// round 5
// speedup vs baseline: 1.9222x; 1.0398x over previous
#include <cuda_runtime.h>
#include <cuda_bf16.h>
#include <math.h>
#include <stdint.h>

#define B_    128
#define L_    512
#define D_    128
#define H_    8
#define E_    16
#define DFF_  512
#define LP_   514

// ---------------- fp32 scratch ----------------
__device__ float g_MarkT[B_*L_*D_];
__device__ float g_H    [B_*L_*D_];
__device__ float g_T1   [B_*L_*D_];
__device__ float g_T2   [B_*L_*D_];
__device__ float g_F    [B_*D_*128];
__device__ float g_PE   [512*128];
__device__ float g_CM   [B_*D_];

// ---------------- bf16 hi/lo activation scratch ----------------
__device__ __nv_bfloat16 g_Xh[B_*LP_*D_], g_Xl[B_*LP_*D_];     // conv input
__device__ __nv_bfloat16 g_Hh[B_*L_*D_],  g_Hl[B_*L_*D_];      // hidden
__device__ __nv_bfloat16 g_Qh[B_*L_*D_],  g_Ql[B_*L_*D_];      // Wq out / iDFT out (flat)
__device__ __nv_bfloat16 g_QTh[B_*L_*D_], g_QTl[B_*L_*D_];     // Q transposed (b,d,l)
__device__ __nv_bfloat16 g_Sh[B_*D_*128], g_Sl[B_*D_*128];     // mixed coeffs
__device__ __nv_bfloat16 g_Uh[B_*L_*DFF_], g_Ul[B_*L_*DFF_];   // FFN hidden

// ---------------- bf16 weights (hi/lo split), [N, K] row-major -------------
__device__ __nv_bfloat16 g_cw_h[128*384], g_cw_l[128*384];
__device__ __nv_bfloat16 g_fb_h[128*512], g_fb_l[128*512];
__device__ __nv_bfloat16 g_ib_h[512*128], g_ib_l[512*128];
__device__ __nv_bfloat16 g_wq_h[2*128*128], g_wq_l[2*128*128];
__device__ __nv_bfloat16 g_wo_h[2*128*128], g_wo_l[2*128*128];
__device__ __nv_bfloat16 g_w1_h[2*512*128], g_w1_l[2*512*128];
__device__ __nv_bfloat16 g_w2_h[2*128*512], g_w2_l[2*128*512];

__device__ __forceinline__ float geluf(float v) {
    return 0.5f * v * (1.0f + erff(v * 0.7071067811865476f));
}
__device__ __forceinline__ void fsplit(float x, __nv_bfloat16& h, __nv_bfloat16& l) {
    h = __float2bfloat16_rn(x);
    l = __float2bfloat16_rn(x - __bfloat162float(h));
}
__device__ __forceinline__ uint32_t pack2(__nv_bfloat16 a, __nv_bfloat16 b) {
    return (uint32_t)__bfloat16_as_ushort(a) | ((uint32_t)__bfloat16_as_ushort(b) << 16);
}
__device__ __forceinline__ uint32_t smem_u32(const void* p) {
    uint32_t a;
    asm("{ .reg .u64 t; cvta.to.shared.u64 t, %1; cvt.u32.u64 %0, t; }" : "=r"(a) : "l"(p));
    return a;
}
__device__ __forceinline__ void ldsm4(uint32_t* r, uint32_t a) {
    asm volatile("ldmatrix.sync.aligned.m8n8.x4.shared.b16 {%0,%1,%2,%3}, [%4];"
        : "=r"(r[0]), "=r"(r[1]), "=r"(r[2]), "=r"(r[3]) : "r"(a));
}
__device__ __forceinline__ void mma16816(float* c, const uint32_t* a, const uint32_t* b) {
    asm volatile(
        "mma.sync.aligned.m16n8k16.row.col.f32.bf16.bf16.f32 "
        "{%0,%1,%2,%3}, {%4,%5,%6,%7}, {%8,%9}, {%0,%1,%2,%3};"
        : "+f"(c[0]), "+f"(c[1]), "+f"(c[2]), "+f"(c[3])
        : "r"(a[0]), "r"(a[1]), "r"(a[2]), "r"(a[3]), "r"(b[0]), "r"(b[1]));
}
#define CP16(d, s)   asm volatile("cp.async.cg.shared.global [%0], [%1], 16;" :: "r"(d), "l"(s))
#define CPCOMMIT()   asm volatile("cp.async.commit_group;" ::: "memory")
#define CPWAIT1()    asm volatile("cp.async.wait_group 1;" ::: "memory")

// tile row = 32 halves = 64B = 4x16B chunks; swizzle chunk ^= (row>>1)&3
__device__ __forceinline__ uint32_t sw32(int row, int ch) {
    return (uint32_t)(row * 64) + (uint32_t)(((ch ^ ((row >> 1) & 3)) << 4));
}

// ---------------- prep: weights -> bf16 hi/lo [N,K]; PE table --------------
__global__ void k_prep(const float* __restrict__ conv_w, const float* __restrict__ Wq,
                       const float* __restrict__ Wo, const float* __restrict__ W1,
                       const float* __restrict__ W2) {
    int idx = blockIdx.x * 256 + threadIdx.x;   // 65536 total
    __nv_bfloat16 h, l;
    if (idx < 49152) {   // conv: N=128 (dout), K=384 (s*128+din)
        int n = idx / 384, k = idx - n*384;
        int s = k >> 7, din = k & 127;
        fsplit(conv_w[n*384 + din*3 + s], h, l);
        g_cw_h[idx] = h; g_cw_l[idx] = l;
    }
    {   // forward DFT basis: N=128 (coeff), K=512 (t)
        int n = idx >> 9, t = idx & 511, m = n & 63;
        float x = (float)(m * t) * (1.0f/256.0f);
        float v = (n < 64) ? cospif(x) : -sinpif(x);
        fsplit(v, h, l); g_fb_h[idx] = h; g_fb_l[idx] = l;
    }
    {   // inverse DFT basis: N=512 (t), K=128 (coeff)
        int t = idx >> 7, n = idx & 127, m = n & 63;
        float x = (float)(m * t) * (1.0f/256.0f);
        float v;
        if (n == 0)       v = 1.0f/512.0f;
        else if (n < 64)  v = cospif(x) * (2.0f/512.0f);
        else if (n == 64) v = 0.0f;
        else              v = -sinpif(x) * (2.0f/512.0f);
        fsplit(v, h, l); g_ib_h[idx] = h; g_ib_l[idx] = l;
    }
    #pragma unroll
    for (int ly = 0; ly < 2; ly++) {
        if (idx < 16384) {
            int n = idx >> 7, k = idx & 127;
            fsplit(Wq[ly*16384 + k*128 + n], h, l);
            g_wq_h[ly*16384 + idx] = h; g_wq_l[ly*16384 + idx] = l;
            fsplit(Wo[ly*16384 + k*128 + n], h, l);
            g_wo_h[ly*16384 + idx] = h; g_wo_l[ly*16384 + idx] = l;
        }
        {   // W1: N=512, K=128
            int n = idx >> 7, k = idx & 127;
            fsplit(W1[ly*65536 + k*512 + n], h, l);
            g_w1_h[ly*65536 + idx] = h; g_w1_l[ly*65536 + idx] = l;
        }
        {   // W2: N=128, K=512
            int n = idx >> 9, k = idx & 511;
            fsplit(W2[ly*65536 + k*128 + n], h, l);
            g_w2_h[ly*65536 + idx] = h; g_w2_l[ly*65536 + idx] = l;
        }
    }
    {   // PE
        int t = idx >> 7, d = idx & 127;
        int i2 = d & ~1;
        float div = expf((float)i2 * (-9.210340371976184f / 128.0f));
        float a = (float)t * div;
        g_PE[idx] = (d & 1) ? cosf(a) : sinf(a);
    }
}

// ---------------- input transpose: fp32 (B,D,L) -> bf16 pair (B,L+2,D) -----
__global__ void k_transpose(const float* __restrict__ x_enc,
                            const float* __restrict__ mark) {
    __shared__ float tile [32][33];
    __shared__ float tileM[32][33];
    int b = blockIdx.z;
    int d0 = blockIdx.y * 32, l0 = blockIdx.x * 32;
    int tx = threadIdx.x, ty = threadIdx.y;
    const float* xb = x_enc + b*65536;
    const float* mb = mark  + b*65536;
    #pragma unroll
    for (int i = ty; i < 32; i += 8) {
        tile [i][tx] = xb[(d0+i)*512 + l0 + tx];
        tileM[i][tx] = mb[(d0+i)*512 + l0 + tx];
    }
    __syncthreads();
    float* mo = g_MarkT + b*65536;
    #pragma unroll
    for (int i = ty; i < 32; i += 8) {
        int oi = b*LP_*128 + (l0+i+1)*128 + d0+tx;
        __nv_bfloat16 h, l; fsplit(tile[tx][i], h, l);
        g_Xh[oi] = h; g_Xl[oi] = l;
        mo[(l0+i)*128 + d0+tx] = tileM[tx][i];
    }
}
__global__ void k_edges(const float* __restrict__ x_enc) {
    int idx = blockIdx.x*256 + threadIdx.x;
    if (idx < B_*D_) {
        int b = idx >> 7, d = idx & 127;
        __nv_bfloat16 h, l;
        fsplit(x_enc[b*65536 + d*512 + 511], h, l);
        g_Xh[b*LP_*128 + d] = h; g_Xl[b*LP_*128 + d] = l;
        fsplit(x_enc[b*65536 + d*512], h, l);
        g_Xh[b*LP_*128 + 513*128 + d] = h; g_Xl[b*LP_*128 + 513*128 + d] = l;
    }
}

// ---------------- bf16 pair transpose (b,l,d) -> (b,d,l) ----------------
__global__ void k_tq() {
    __shared__ __nv_bfloat16 th[32][34], tl[32][34];
    int b = blockIdx.z;
    int l0 = blockIdx.x * 32, d0 = blockIdx.y * 32;
    int tx = threadIdx.x, ty = threadIdx.y;
    #pragma unroll
    for (int i = ty; i < 32; i += 8) {
        int gi = b*65536 + (l0+i)*128 + d0 + tx;
        th[i][tx] = g_Qh[gi]; tl[i][tx] = g_Ql[gi];
    }
    __syncthreads();
    #pragma unroll
    for (int i = ty; i < 32; i += 8) {
        int go = b*65536 + (d0+i)*512 + l0 + tx;
        g_QTh[go] = th[tx][i]; g_QTl[go] = tl[tx][i];
    }
}

// ---------------- HMMA split-bf16 GEMM, cp.async 3-stage --------------------
// CTA tile 64(M) x 128(N); 8 warps of 32x32; 3 CTAs/SM.
// C = epi( A(row,:) @ B^T ); A,B bf16 hi/lo; K-chunk 32.
// A(row,k) = Ax[(row>>absh)*abstr + (row&mask)*arstr + k]
// EPI bits: 1=+bias[col], 2=+res, 4=gelu, 8=+PE, 16=skip fp32 C store
// WRB: also write bf16 hi/lo result to Ch/Cl
// SMEM/stage (24KB): Ah@0(4K) Al@4K Bh@8K(8K) Bl@16K; 3 stages = 72KB.
template<int EPI, int WRB>
__global__ void __launch_bounds__(256, 3) k_tgemm(
    const __nv_bfloat16* __restrict__ Ah, const __nv_bfloat16* __restrict__ Al,
    const __nv_bfloat16* __restrict__ Bh, const __nv_bfloat16* __restrict__ Bl,
    const float* __restrict__ bias, const float* __restrict__ res,
    float* __restrict__ C, __nv_bfloat16* __restrict__ Ch, __nv_bfloat16* __restrict__ Cl,
    int K, int ldc, int absh, int abstr, int arstr)
{
    extern __shared__ char sm[];
    const uint32_t sU = smem_u32(sm);
    const int tid = threadIdx.x, wid = tid >> 5, lane = tid & 31;
    const int rowBase = blockIdx.x * 64, colBase = blockIdx.y * 128;
    const int amask = (1 << absh) - 1;

    float acc[2][4][4];
    #pragma unroll
    for (int i = 0; i < 2; i++)
        #pragma unroll
        for (int j = 0; j < 4; j++)
            #pragma unroll
            for (int q = 0; q < 4; q++) acc[i][j][q] = 0.f;

    const int nc = K >> 5;

    // per-thread A-load slot (i=0,1): row = tid>>2 (0..63), ch = tid&3
    const int a_row = tid >> 2, a_ch = tid & 3;
    const uint32_t a_sw = sw32(a_row, a_ch);
    int a_rg = rowBase + a_row;
    const long a_base = (long)(a_rg >> absh)*abstr + (long)(a_rg & amask)*arstr + a_ch*8;
    // B-load slots (i=2..5): rows 0..127
    const int b_row0 = tid >> 2, b_row1 = 64 + (tid >> 2);
    const uint32_t b_sw0 = sw32(b_row0, a_ch), b_sw1 = sw32(b_row1, a_ch);
    const long b_base0 = (long)(colBase + b_row0)*K + a_ch*8;
    const long b_base1 = (long)(colBase + b_row1)*K + a_ch*8;

    auto load_chunk = [&](int stage, int k0) {
        uint32_t sb = sU + stage * 24576;
        CP16(sb +         a_sw, Ah + a_base + k0);
        CP16(sb +  4096 + a_sw, Al + a_base + k0);
        CP16(sb +  8192 + b_sw0, Bh + b_base0 + k0);
        CP16(sb +  8192 + b_sw1, Bh + b_base1 + k0);
        CP16(sb + 16384 + b_sw0, Bl + b_base0 + k0);
        CP16(sb + 16384 + b_sw1, Bl + b_base1 + k0);
    };

    load_chunk(0, 0);  CPCOMMIT();
    load_chunk(1, 32); CPCOMMIT();

    const int mrow = (wid & 1) * 32;
    const int ncol = (wid >> 1) * 32;
    // precomputed ldsm lane addressing
    const int a_lr  = mrow + (lane & 15);          // A frag row (f adds 16)
    const int a_lc  = lane >> 4;                   // A k-half
    const int b_lr  = ncol + (lane & 7) + ((lane & 16) ? 8 : 0);
    const int b_lc  = (lane >> 3) & 1;
    int stage = 0;

    for (int c = 0; c < nc; c++) {
        CPWAIT1();
        __syncthreads();
        if (c + 2 < nc) {
            int ns = stage + 2; if (ns >= 3) ns -= 3;
            load_chunk(ns, (c + 2) * 32);
        }
        CPCOMMIT();

        uint32_t sb = sU + stage * 24576;
        #pragma unroll
        for (int ks = 0; ks < 2; ks++) {
            uint32_t af[2][4], bhf[2][4], blf[2][4];
            // issue all hi/lo B and hi A ldsm upfront
            #pragma unroll
            for (int g = 0; g < 2; g++) {
                int r = b_lr + g*16, ci = ks*2 + b_lc;
                ldsm4(bhf[g], sb +  8192 + sw32(r, ci));
                ldsm4(blf[g], sb + 16384 + sw32(r, ci));
            }
            #pragma unroll
            for (int f = 0; f < 2; f++) {
                int r = a_lr + f*16, ci = ks*2 + a_lc;
                ldsm4(af[f], sb + sw32(r, ci));
            }
            #pragma unroll
            for (int mi = 0; mi < 2; mi++)
                #pragma unroll
                for (int ni = 0; ni < 4; ni++)
                    mma16816(acc[mi][ni], af[mi], &bhf[ni >> 1][(ni & 1) * 2]);
            #pragma unroll
            for (int mi = 0; mi < 2; mi++)
                #pragma unroll
                for (int ni = 0; ni < 4; ni++)
                    mma16816(acc[mi][ni], af[mi], &blf[ni >> 1][(ni & 1) * 2]);
            #pragma unroll
            for (int f = 0; f < 2; f++) {
                int r = a_lr + f*16, ci = ks*2 + a_lc;
                ldsm4(af[f], sb + 4096 + sw32(r, ci));
            }
            #pragma unroll
            for (int mi = 0; mi < 2; mi++)
                #pragma unroll
                for (int ni = 0; ni < 4; ni++)
                    mma16816(acc[mi][ni], af[mi], &bhf[ni >> 1][(ni & 1) * 2]);
        }
        if (++stage >= 3) stage -= 3;
    }

    // ---- epilogue ----
    #pragma unroll
    for (int mi = 0; mi < 2; mi++) {
        #pragma unroll
        for (int half = 0; half < 2; half++) {
            int grow = rowBase + mrow + mi*16 + (lane >> 2) + half*8;
            #pragma unroll
            for (int ni = 0; ni < 4; ni++) {
                int gcol = colBase + ncol + ni*8 + (lane & 3)*2;
                float v0 = acc[mi][ni][half*2 + 0];
                float v1 = acc[mi][ni][half*2 + 1];
                if (EPI & 1) { v0 += bias[gcol]; v1 += bias[gcol + 1]; }
                if (EPI & 8) {
                    int pbi = (grow & 511)*128 + (gcol & 127);
                    v0 += g_PE[pbi]; v1 += g_PE[pbi + 1];
                }
                long oidx = (long)grow * ldc + gcol;
                if (EPI & 2) {
                    float2 rr = *(const float2*)(res + oidx);
                    v0 += rr.x; v1 += rr.y;
                }
                if (EPI & 4) { v0 = geluf(v0); v1 = geluf(v1); }
                if (!(EPI & 16)) {
                    float2 o; o.x = v0; o.y = v1;
                    *(float2*)(C + oidx) = o;
                }
                if (WRB) {
                    __nv_bfloat16 h0,l0,h1,l1;
                    fsplit(v0,h0,l0); fsplit(v1,h1,l1);
                    *(uint32_t*)(Ch + oidx) = pack2(h0,h1);
                    *(uint32_t*)(Cl + oidx) = pack2(l0,l1);
                }
            }
        }
    }
}

// ---------------- complex mode mixing (fp32 in, bf16 pair out) -------------
__global__ void k_mix(const float* __restrict__ fwr,
                      const float* __restrict__ fwi, int layer) {
    int b = blockIdx.x, hh = blockIdx.y;
    int m = threadIdx.x;
    const float* wr = fwr + (size_t)((layer*H_ + hh)*E_*E_) * 64;
    const float* wi = fwi + (size_t)((layer*H_ + hh)*E_*E_) * 64;
    float sr[E_], si[E_];
    #pragma unroll
    for (int o = 0; o < E_; o++) { sr[o] = 0.f; si[o] = 0.f; }
    const float* Fb = g_F + (b*128 + hh*16) * 128;
    #pragma unroll
    for (int e = 0; e < E_; e++) {
        float fre = Fb[e*128 + m];
        float fim = Fb[e*128 + 64 + m];
        #pragma unroll
        for (int o = 0; o < E_; o++) {
            float cr = wr[(e*E_ + o)*64 + m];
            float ci = wi[(e*E_ + o)*64 + m];
            sr[o] += fre*cr - fim*ci;
            si[o] += fre*ci + fim*cr;
        }
    }
    int base = (b*128 + hh*16) * 128;
    #pragma unroll
    for (int o = 0; o < E_; o++) {
        __nv_bfloat16 h, l;
        fsplit(sr[o], h, l);
        g_Sh[base + o*128 + m] = h;      g_Sl[base + o*128 + m] = l;
        fsplit(si[o], h, l);
        g_Sh[base + o*128 + 64 + m] = h; g_Sl[base + o*128 + 64 + m] = l;
    }
}

// ---------------- series_decomp: fp32 + bf16-pair outputs ------------------
__global__ void k_movsub(const float* __restrict__ X, float* __restrict__ Out,
                         __nv_bfloat16* __restrict__ Oh, __nv_bfloat16* __restrict__ Ol) {
    __shared__ float sh[88 * 128];
    int b = blockIdx.x, t0 = blockIdx.y * 64;
    int d = threadIdx.x;
    const float* Xb = X + b*65536;
    #pragma unroll 4
    for (int r = 0; r < 88; r++) {
        int t = t0 + r - 12;
        t = max(0, min(511, t));
        sh[r*128 + d] = Xb[t*128 + d];
    }
    float s = 0.f;
    #pragma unroll 4
    for (int r = 0; r < 88; r++) { s += sh[r*128 + d]; sh[r*128 + d] = s; }
    #pragma unroll 4
    for (int tt = 0; tt < 64; tt++) {
        int r = tt + 12;
        float hi = sh[(r+12)*128 + d];
        float lo = (r >= 13) ? sh[(r-13)*128 + d] : 0.f;
        float v = Xb[(t0+tt)*128 + d] - (hi - lo) * (1.0f/25.0f);
        int oi = b*65536 + (t0+tt)*128 + d;
        Out[oi] = v;
        __nv_bfloat16 h, l; fsplit(v, h, l);
        Oh[oi] = h; Ol[oi] = l;
    }
}

// ---------------- LayerNorm ----------------
__global__ void k_ln(const float* __restrict__ X, const float* __restrict__ g,
                     const float* __restrict__ be, float* __restrict__ Out) {
    int row  = blockIdx.x*8 + (threadIdx.x >> 5);
    int lane = threadIdx.x & 31;
    const float* xr = X + (size_t)row * 128;
    float v[4];
    float s = 0.f;
    #pragma unroll
    for (int i = 0; i < 4; i++) { v[i] = xr[lane + i*32]; s += v[i]; }
    #pragma unroll
    for (int o = 16; o > 0; o >>= 1) s += __shfl_xor_sync(0xffffffffu, s, o);
    float mu = s * (1.0f/128.0f);
    float q = 0.f;
    #pragma unroll
    for (int i = 0; i < 4; i++) { float dl = v[i] - mu; q += dl*dl; }
    #pragma unroll
    for (int o = 16; o > 0; o >>= 1) q += __shfl_xor_sync(0xffffffffu, q, o);
    float rstd = rsqrtf(q * (1.0f/128.0f) + 1e-5f);
    float* orow = Out + (size_t)row * 128;
    #pragma unroll
    for (int i = 0; i < 4; i++) {
        int d = lane + i*32;
        orow[d] = (v[i] - mu) * rstd * g[d] + be[d];
    }
}

__global__ void k_zero(float* p, int n) {
    int i = blockIdx.x*256 + threadIdx.x;
    if (i < n) p[i] = 0.f;
}
__global__ void k_colmean(const float* __restrict__ HN) {
    int b = blockIdx.x, t0 = blockIdx.y * 64, d = threadIdx.x;
    const float* Xb = HN + b*65536;
    float s = 0.f;
    #pragma unroll 8
    for (int tt = 0; tt < 64; tt++) s += Xb[(t0+tt)*128 + d];
    atomicAdd(&g_CM[b*128 + d], s);
}
__global__ void k_final(const float* __restrict__ HN, const float* __restrict__ pw,
                        const float* __restrict__ pb, float* __restrict__ out) {
    int b = blockIdx.x, tid = threadIdx.x;
    const float* hb = HN + b*65536;
    const float* mb = g_MarkT + b*65536;
    float s = 0.f;
    for (int i = tid; i < 65536; i += 256) {
        float v = hb[i] - g_CM[b*128 + (i & 127)] * (1.0f/512.0f);
        s += geluf(v) * mb[i] * pw[i];
    }
    __shared__ float red[256];
    red[tid] = s; __syncthreads();
    #pragma unroll
    for (int o = 128; o > 0; o >>= 1) {
        if (tid < o) red[tid] += red[tid + o];
        __syncthreads();
    }
    if (tid == 0) out[b] = red[0] + pb[0];
}

// ---------------- host orchestration ----------------
#define SMB 73728

extern "C" void kernel_launch(void* const* d_in, const int* in_sizes, int n_in,
                              void* d_out, int out_size) {
    const float* x_enc  = (const float*)d_in[0];
    const float* mark   = (const float*)d_in[1];
    const float* conv_w = (const float*)d_in[4];
    const float* Wq     = (const float*)d_in[5];
    const float* bq     = (const float*)d_in[6];
    const float* Wo     = (const float*)d_in[7];
    const float* bo     = (const float*)d_in[8];
    const float* fwr    = (const float*)d_in[9];
    const float* fwi    = (const float*)d_in[10];
    const float* W1     = (const float*)d_in[11];
    const float* W2     = (const float*)d_in[12];
    const float* ln_g   = (const float*)d_in[13];
    const float* ln_b   = (const float*)d_in[14];
    const float* pw     = (const float*)d_in[15];
    const float* pb     = (const float*)d_in[16];
    float* out = (float*)d_out;

    cudaFuncSetAttribute(k_tgemm<8,1>,  cudaFuncAttributeMaxDynamicSharedMemorySize, SMB);
    cudaFuncSetAttribute(k_tgemm<17,1>, cudaFuncAttributeMaxDynamicSharedMemorySize, SMB);
    cudaFuncSetAttribute(k_tgemm<0,0>,  cudaFuncAttributeMaxDynamicSharedMemorySize, SMB);
    cudaFuncSetAttribute(k_tgemm<16,1>, cudaFuncAttributeMaxDynamicSharedMemorySize, SMB);
    cudaFuncSetAttribute(k_tgemm<3,0>,  cudaFuncAttributeMaxDynamicSharedMemorySize, SMB);
    cudaFuncSetAttribute(k_tgemm<20,1>, cudaFuncAttributeMaxDynamicSharedMemorySize, SMB);
    cudaFuncSetAttribute(k_tgemm<2,0>,  cudaFuncAttributeMaxDynamicSharedMemorySize, SMB);

    float *pH, *pT1, *pT2, *pF, *pCM;
    cudaGetSymbolAddress((void**)&pH,   g_H);
    cudaGetSymbolAddress((void**)&pT1,  g_T1);
    cudaGetSymbolAddress((void**)&pT2,  g_T2);
    cudaGetSymbolAddress((void**)&pF,   g_F);
    cudaGetSymbolAddress((void**)&pCM,  g_CM);
    __nv_bfloat16 *xh,*xl,*hh,*hl,*qh,*ql,*qth,*qtl,*sh,*sl,*uh,*ul;
    cudaGetSymbolAddress((void**)&xh,  g_Xh);  cudaGetSymbolAddress((void**)&xl,  g_Xl);
    cudaGetSymbolAddress((void**)&hh,  g_Hh);  cudaGetSymbolAddress((void**)&hl,  g_Hl);
    cudaGetSymbolAddress((void**)&qh,  g_Qh);  cudaGetSymbolAddress((void**)&ql,  g_Ql);
    cudaGetSymbolAddress((void**)&qth, g_QTh); cudaGetSymbolAddress((void**)&qtl, g_QTl);
    cudaGetSymbolAddress((void**)&sh,  g_Sh);  cudaGetSymbolAddress((void**)&sl,  g_Sl);
    cudaGetSymbolAddress((void**)&uh,  g_Uh);  cudaGetSymbolAddress((void**)&ul,  g_Ul);
    __nv_bfloat16 *cwh,*cwl,*fbh,*fbl,*ibh,*ibl,*wqh,*wql,*woh,*wol,*w1h,*w1l,*w2h,*w2l;
    cudaGetSymbolAddress((void**)&cwh, g_cw_h); cudaGetSymbolAddress((void**)&cwl, g_cw_l);
    cudaGetSymbolAddress((void**)&fbh, g_fb_h); cudaGetSymbolAddress((void**)&fbl, g_fb_l);
    cudaGetSymbolAddress((void**)&ibh, g_ib_h); cudaGetSymbolAddress((void**)&ibl, g_ib_l);
    cudaGetSymbolAddress((void**)&wqh, g_wq_h); cudaGetSymbolAddress((void**)&wql, g_wq_l);
    cudaGetSymbolAddress((void**)&woh, g_wo_h); cudaGetSymbolAddress((void**)&wol, g_wo_l);
    cudaGetSymbolAddress((void**)&w1h, g_w1_h); cudaGetSymbolAddress((void**)&w1l, g_w1_l);
    cudaGetSymbolAddress((void**)&w2h, g_w2_h); cudaGetSymbolAddress((void**)&w2l, g_w2_l);

    k_prep<<<256, 256>>>(conv_w, Wq, Wo, W1, W2);
    k_transpose<<<dim3(16,4,128), dim3(32,8)>>>(x_enc, mark);
    k_edges<<<64, 256>>>(x_enc);

    // TokenEmbedding conv (K=384) + PE -> fp32 H + bf16 pair H
    k_tgemm<8,1><<<dim3(1024,1), 256, SMB>>>(
        xh, xl, cwh, cwl, nullptr, nullptr, pH, hh, hl,
        384, 128, 9, LP_*128, 128);

    for (int l = 0; l < 2; l++) {
        // Q = H @ Wq + bq -> bf16 pair only
        k_tgemm<17,1><<<dim3(1024,1), 256, SMB>>>(
            hh, hl, wqh + l*16384, wql + l*16384, bq + l*128, nullptr,
            nullptr, qh, ql, 128, 128, 30, 0, 128);
        // transpose Q (b,l,d) -> (b,d,l)
        k_tq<<<dim3(16,4,128), dim3(32,8)>>>();
        // forward DFT -> fp32 F
        k_tgemm<0,0><<<dim3(256,1), 256, SMB>>>(
            qth, qtl, fbh, fbl, nullptr, nullptr, pF, nullptr, nullptr,
            512, 128, 30, 0, 512);
        // complex mode mixing -> bf16 pair S
        k_mix<<<dim3(128,8), 64>>>(fwr, fwi, l);
        // inverse DFT -> bf16 pair flat (== scrambled view(B,L,-1))
        k_tgemm<16,1><<<dim3(256,4), 256, SMB>>>(
            sh, sl, ibh, ibl, nullptr, nullptr, nullptr, qh, ql,
            128, 512, 30, 0, 128);
        // out proj + bias + residual -> fp32 T2
        k_tgemm<3,0><<<dim3(1024,1), 256, SMB>>>(
            qh, ql, woh + l*16384, wol + l*16384, bo + l*128, pH,
            pT2, nullptr, nullptr, 128, 128, 30, 0, 128);
        // decomp1 -> fp32 H + bf16 pair H
        k_movsub<<<dim3(128,8), 128>>>(pT2, pH, hh, hl);
        // FFN up + gelu -> bf16 pair U
        k_tgemm<20,1><<<dim3(1024,4), 256, SMB>>>(
            hh, hl, w1h + l*65536, w1l + l*65536, nullptr, nullptr,
            nullptr, uh, ul, 128, 512, 30, 0, 128);
        // FFN down + residual -> fp32 T2
        k_tgemm<2,0><<<dim3(1024,1), 256, SMB>>>(
            uh, ul, w2h + l*65536, w2l + l*65536, nullptr, pH,
            pT2, nullptr, nullptr, 512, 128, 30, 0, 512);
        // decomp2 -> fp32 H + bf16 pair H
        k_movsub<<<dim3(128,8), 128>>>(pT2, pH, hh, hl);
    }

    k_ln<<<8192, 256>>>(pH, ln_g, ln_b, pT1);
    k_zero<<<64, 256>>>(pCM, B_*D_);
    k_colmean<<<dim3(128,8), 128>>>(pT1);
    k_final<<<128, 256>>>(pT1, pw, pb, out);
}